// round 5
// baseline (speedup 1.0000x reference)
#include <cuda_runtime.h>
#include <math.h>
#include <stdint.h>

// Problem constants (fixed by the dataset)
#define NMAX 50000
#define DH   128

// Scratch (allocation-free rule: __device__ globals)
__device__ float g_agg[(size_t)NMAX * DH];
__device__ float g_h1 [(size_t)NMAX * DH];
__device__ float g_h2 [(size_t)NMAX * DH];
// Packed per-node head table: [Am(128) | Cv(128) | Bm(128) | Dv(128)]
__device__ float g_S  [(size_t)NMAX * 512];

// ---------------------------------------------------------------------------
// zero kernel (float4)
// ---------------------------------------------------------------------------
__global__ void k_zero(float* __restrict__ p, int n4)
{
    int i = blockIdx.x * blockDim.x + threadIdx.x;
    if (i < n4) reinterpret_cast<float4*>(p)[i] = make_float4(0.f, 0.f, 0.f, 0.f);
}

// ---------------------------------------------------------------------------
// scatter: agg[dst] += feat[src], warp per edge, float4 per lane, vector RED
// edge_index is int32 (JAX x64-disabled downcasts int64 -> int32)
// ---------------------------------------------------------------------------
__global__ void k_scatter(const float* __restrict__ feat,
                          const int* __restrict__ ei,
                          int E, float* __restrict__ agg)
{
    int g = blockIdx.x * blockDim.x + threadIdx.x;
    int e = g >> 5, lane = g & 31;
    if (e >= E) return;
    int s = ei[e];
    int d = ei[(size_t)E + e];
    float4 v = *reinterpret_cast<const float4*>(&feat[(size_t)s * DH + lane * 4]);
    float* dst = &agg[(size_t)d * DH + lane * 4];
    asm volatile("red.global.add.v4.f32 [%0], {%1, %2, %3, %4};"
                 :: "l"(dst), "f"(v.x), "f"(v.y), "f"(v.z), "f"(v.w)
                 : "memory");
}

// ---------------------------------------------------------------------------
// Generic 128-wide GEMM:
//   C[m, 0:128] (+= over up to 2 phases) = A0@W0 (+ A1@W1) (+ bias) (relu)
// BM=128, BN=128, BK=16, 256 threads, 8x8 per-thread microtile.
// C has row stride ldc (128 for conv layers, 512 for the packed head table).
// ---------------------------------------------------------------------------
__global__ __launch_bounds__(256)
void k_gemm(const float* __restrict__ A0, const float* __restrict__ W0,
            const float* __restrict__ A1, const float* __restrict__ W1,
            const float* __restrict__ bias, float* __restrict__ C,
            int M, int ldc, int relu)
{
    __shared__ float shA[16][128];   // [k][m]
    __shared__ float shW[16][128];   // [k][n]

    int tid = threadIdx.x;
    int tx = tid & 15;        // col group
    int ty = tid >> 4;        // row group
    int m0 = blockIdx.x * 128;

    float acc[8][8];
#pragma unroll
    for (int i = 0; i < 8; i++)
#pragma unroll
        for (int j = 0; j < 8; j++) acc[i][j] = 0.f;

#pragma unroll 1
    for (int phase = 0; phase < 2; ++phase) {
        const float* A = phase ? A1 : A0;
        const float* W = phase ? W1 : W0;
        if (A == nullptr) break;

#pragma unroll 1
        for (int kk = 0; kk < 128; kk += 16) {
            __syncthreads();
            // Load A tile (128 rows x 16 cols), store transposed shA[k][m]
#pragma unroll
            for (int r = 0; r < 2; ++r) {
                int f   = tid + r * 256;      // 0..511 float4 ids
                int row = f >> 2;             // 0..127
                int c4  = (f & 3) << 2;       // 0,4,8,12
                float4 v = make_float4(0.f, 0.f, 0.f, 0.f);
                if (m0 + row < M)
                    v = *reinterpret_cast<const float4*>(
                        &A[(size_t)(m0 + row) * DH + kk + c4]);
                shA[c4 + 0][row] = v.x;
                shA[c4 + 1][row] = v.y;
                shA[c4 + 2][row] = v.z;
                shA[c4 + 3][row] = v.w;
            }
            // Load W tile (16 rows x 128 cols), natural layout
#pragma unroll
            for (int r = 0; r < 2; ++r) {
                int f  = tid + r * 256;
                int k  = f >> 5;              // 0..15
                int n4 = (f & 31) << 2;       // 0..124
                *reinterpret_cast<float4*>(&shW[k][n4]) =
                    *reinterpret_cast<const float4*>(&W[(size_t)(kk + k) * DH + n4]);
            }
            __syncthreads();

#pragma unroll
            for (int k = 0; k < 16; ++k) {
                float4 a0 = *reinterpret_cast<float4*>(&shA[k][ty * 8]);
                float4 a1 = *reinterpret_cast<float4*>(&shA[k][ty * 8 + 4]);
                float4 b0 = *reinterpret_cast<float4*>(&shW[k][tx * 8]);
                float4 b1 = *reinterpret_cast<float4*>(&shW[k][tx * 8 + 4]);
                float av[8] = {a0.x, a0.y, a0.z, a0.w, a1.x, a1.y, a1.z, a1.w};
                float bv[8] = {b0.x, b0.y, b0.z, b0.w, b1.x, b1.y, b1.z, b1.w};
#pragma unroll
                for (int i = 0; i < 8; i++)
#pragma unroll
                    for (int j = 0; j < 8; j++)
                        acc[i][j] += av[i] * bv[j];
            }
        }
    }

    // Epilogue
#pragma unroll
    for (int i = 0; i < 8; i++) {
        int m = m0 + ty * 8 + i;
        if (m < M) {
#pragma unroll
            for (int j = 0; j < 8; j++) {
                int col = tx * 8 + j;
                float v = acc[i][j];
                if (bias) v += bias[col];
                if (relu) v = fmaxf(v, 0.f);
                C[(size_t)m * ldc + col] = v;
            }
        }
    }
}

// ---------------------------------------------------------------------------
// Edge head: warp per edge.
// mean_e = sum_j relu(Am[s][j] + Bm[d][j] + bm1[j]) * Wm2[j] + bm2
// var_e  = exp(0.5 * (sum_j relu(Cv[s][j] + Dv[d][j] + bv1[j]) * Wv2[j] + bv2))
// ---------------------------------------------------------------------------
__global__ __launch_bounds__(256)
void k_edge(const int* __restrict__ ei,
            const float* __restrict__ S,
            const float* __restrict__ bm1, const float* __restrict__ Wm2,
            const float* __restrict__ bm2,
            const float* __restrict__ bv1, const float* __restrict__ Wv2,
            const float* __restrict__ bv2,
            float* __restrict__ outMean, float* __restrict__ outVar, int E)
{
    int g = blockIdx.x * blockDim.x + threadIdx.x;
    int e = g >> 5, lane = g & 31;
    if (e >= E) return;

    float4 c_bm1 = *reinterpret_cast<const float4*>(&bm1[lane * 4]);
    float4 c_wm2 = *reinterpret_cast<const float4*>(&Wm2[lane * 4]);
    float4 c_bv1 = *reinterpret_cast<const float4*>(&bv1[lane * 4]);
    float4 c_wv2 = *reinterpret_cast<const float4*>(&Wv2[lane * 4]);

    int s = ei[e];
    int d = ei[(size_t)E + e];
    const float* Sp = S + (size_t)s * 512;
    const float* Dp = S + (size_t)d * 512;

    float4 am = *reinterpret_cast<const float4*>(&Sp[lane * 4]);          // Am
    float4 cv = *reinterpret_cast<const float4*>(&Sp[128 + lane * 4]);    // Cv
    float4 bm = *reinterpret_cast<const float4*>(&Dp[256 + lane * 4]);    // Bm
    float4 dv = *reinterpret_cast<const float4*>(&Dp[384 + lane * 4]);    // Dv

    float pm = fmaxf(am.x + bm.x + c_bm1.x, 0.f) * c_wm2.x
             + fmaxf(am.y + bm.y + c_bm1.y, 0.f) * c_wm2.y
             + fmaxf(am.z + bm.z + c_bm1.z, 0.f) * c_wm2.z
             + fmaxf(am.w + bm.w + c_bm1.w, 0.f) * c_wm2.w;
    float pv = fmaxf(cv.x + dv.x + c_bv1.x, 0.f) * c_wv2.x
             + fmaxf(cv.y + dv.y + c_bv1.y, 0.f) * c_wv2.y
             + fmaxf(cv.z + dv.z + c_bv1.z, 0.f) * c_wv2.z
             + fmaxf(cv.w + dv.w + c_bv1.w, 0.f) * c_wv2.w;

#pragma unroll
    for (int off = 16; off > 0; off >>= 1) {
        pm += __shfl_xor_sync(0xFFFFFFFFu, pm, off);
        pv += __shfl_xor_sync(0xFFFFFFFFu, pv, off);
    }
    if (lane == 0) {
        outMean[e] = pm + bm2[0];
        outVar[e]  = expf(0.5f * (pv + bv2[0]));
    }
}

// ---------------------------------------------------------------------------
// kernel_launch
// ---------------------------------------------------------------------------
extern "C" void kernel_launch(void* const* d_in, const int* in_sizes, int n_in,
                              void* d_out, int out_size)
{
    const float* x       = (const float*)d_in[0];
    const int*   ei      = (const int*)d_in[1];
    const float* W1_rel  = (const float*)d_in[2];
    const float* b1      = (const float*)d_in[3];
    const float* W1_root = (const float*)d_in[4];
    const float* W2_rel  = (const float*)d_in[5];
    const float* b2      = (const float*)d_in[6];
    const float* W2_root = (const float*)d_in[7];
    const float* Wm1     = (const float*)d_in[8];
    const float* bm1     = (const float*)d_in[9];
    const float* Wm2     = (const float*)d_in[10];
    const float* bm2     = (const float*)d_in[11];
    const float* Wv1     = (const float*)d_in[12];
    const float* bv1     = (const float*)d_in[13];
    const float* Wv2     = (const float*)d_in[14];
    const float* bv2     = (const float*)d_in[15];

    int N = in_sizes[0] / DH;        // 50000
    int E = in_sizes[1] / 2;         // 800000
    float* out    = (float*)d_out;
    int    Ehalf  = out_size / 2;    // mean in [0,Ehalf), var in [Ehalf, 2*Ehalf)

    float *agg, *h1, *h2, *S;
    cudaGetSymbolAddress((void**)&agg, g_agg);
    cudaGetSymbolAddress((void**)&h1,  g_h1);
    cudaGetSymbolAddress((void**)&h2,  g_h2);
    cudaGetSymbolAddress((void**)&S,   g_S);

    int zeroB    = (N * (DH / 4) + 255) / 256;
    int scatterB = (E * 32 + 255) / 256;
    int gemmB    = (N + 127) / 128;
    int edgeB    = (E * 32 + 255) / 256;

    // Layer 1
    k_zero<<<zeroB, 256>>>(agg, N * (DH / 4));
    k_scatter<<<scatterB, 256>>>(x, ei, E, agg);
    k_gemm<<<gemmB, 256>>>(agg, W1_rel, x, W1_root, b1, h1, N, DH, 1);

    // Layer 2
    k_zero<<<zeroB, 256>>>(agg, N * (DH / 4));
    k_scatter<<<scatterB, 256>>>(h1, ei, E, agg);
    k_gemm<<<gemmB, 256>>>(agg, W2_rel, h1, W2_root, b2, h2, N, DH, 1);

    // Head node tables: S[n] = [ h2@Wm1_top | h2@Wv1_top | h2@Wm1_bot | h2@Wv1_bot ]
    k_gemm<<<gemmB, 256>>>(h2, Wm1,             nullptr, nullptr, nullptr, S + 0,   N, 512, 0);
    k_gemm<<<gemmB, 256>>>(h2, Wv1,             nullptr, nullptr, nullptr, S + 128, N, 512, 0);
    k_gemm<<<gemmB, 256>>>(h2, Wm1 + 128 * DH,  nullptr, nullptr, nullptr, S + 256, N, 512, 0);
    k_gemm<<<gemmB, 256>>>(h2, Wv1 + 128 * DH,  nullptr, nullptr, nullptr, S + 384, N, 512, 0);

    // Edge heads
    k_edge<<<edgeB, 256>>>(ei, S, bm1, Wm2, bm2, bv1, Wv2, bv2,
                           out, out + Ehalf, E);
}

// round 10
// speedup vs baseline: 1.4247x; 1.4247x over previous
#include <cuda_runtime.h>
#include <cuda_bf16.h>
#include <math.h>
#include <stdint.h>

#define NMAX 50000
#define DH   128
#define MTILE 128
#define PADK 136      // bf16 elements per padded SMEM row (272 B)

// ---------------------------------------------------------------------------
// Scratch (__device__ globals; allocation-free rule)
// ---------------------------------------------------------------------------
__device__ float g_agg[(size_t)NMAX * DH];
__device__ float g_h1 [(size_t)NMAX * DH];
__device__ float g_S  [(size_t)NMAX * 512];   // [Am|Cv|Bm|Dv] per node

__device__ __nv_bfloat16 g_xh  [(size_t)NMAX * DH];
__device__ __nv_bfloat16 g_xl  [(size_t)NMAX * DH];
__device__ __nv_bfloat16 g_aggh[(size_t)NMAX * DH];
__device__ __nv_bfloat16 g_aggl[(size_t)NMAX * DH];
__device__ __nv_bfloat16 g_h1h [(size_t)NMAX * DH];
__device__ __nv_bfloat16 g_h1l [(size_t)NMAX * DH];
__device__ __nv_bfloat16 g_h2h [(size_t)NMAX * DH];
__device__ __nv_bfloat16 g_h2l [(size_t)NMAX * DH];
// 8 weight units, each transposed [n][k] 128x128, hi/lo
__device__ __nv_bfloat16 g_Wh[8 * 128 * 128];
__device__ __nv_bfloat16 g_Wl[8 * 128 * 128];

// ---------------------------------------------------------------------------
// helpers
// ---------------------------------------------------------------------------
__device__ __forceinline__ uint32_t smem_to_u32(const void* p) {
    uint32_t a;
    asm("{ .reg .u64 t; cvta.to.shared.u64 t, %1; cvt.u32.u64 %0, t; }"
        : "=r"(a) : "l"(p));
    return a;
}

__device__ __forceinline__ void ldsm_x4(uint32_t* r, uint32_t addr) {
    asm volatile("ldmatrix.sync.aligned.m8n8.x4.shared.b16 {%0,%1,%2,%3}, [%4];"
                 : "=r"(r[0]), "=r"(r[1]), "=r"(r[2]), "=r"(r[3]) : "r"(addr));
}
__device__ __forceinline__ void ldsm_x2(uint32_t* r, uint32_t addr) {
    asm volatile("ldmatrix.sync.aligned.m8n8.x2.shared.b16 {%0,%1}, [%2];"
                 : "=r"(r[0]), "=r"(r[1]) : "r"(addr));
}
__device__ __forceinline__ void mma16816(float* c, const uint32_t* a, const uint32_t* b) {
    asm volatile(
        "mma.sync.aligned.m16n8k16.row.col.f32.bf16.bf16.f32 "
        "{%0,%1,%2,%3}, {%4,%5,%6,%7}, {%8,%9}, {%0,%1,%2,%3};"
        : "+f"(c[0]), "+f"(c[1]), "+f"(c[2]), "+f"(c[3])
        : "r"(a[0]), "r"(a[1]), "r"(a[2]), "r"(a[3]), "r"(b[0]), "r"(b[1]));
}

// ---------------------------------------------------------------------------
// zero kernel (float4)
// ---------------------------------------------------------------------------
__global__ void k_zero(float* __restrict__ p, int n4)
{
    int i = blockIdx.x * blockDim.x + threadIdx.x;
    if (i < n4) reinterpret_cast<float4*>(p)[i] = make_float4(0.f, 0.f, 0.f, 0.f);
}

// ---------------------------------------------------------------------------
// scatter: agg[dst] += feat[src], warp per edge, float4 per lane, vector RED
// ---------------------------------------------------------------------------
__global__ void k_scatter(const float* __restrict__ feat,
                          const int* __restrict__ ei,
                          int E, float* __restrict__ agg)
{
    int g = blockIdx.x * blockDim.x + threadIdx.x;
    int e = g >> 5, lane = g & 31;
    if (e >= E) return;
    int s = ei[e];
    int d = ei[(size_t)E + e];
    float4 v = *reinterpret_cast<const float4*>(&feat[(size_t)s * DH + lane * 4]);
    float* dst = &agg[(size_t)d * DH + lane * 4];
    asm volatile("red.global.add.v4.f32 [%0], {%1, %2, %3, %4};"
                 :: "l"(dst), "f"(v.x), "f"(v.y), "f"(v.z), "f"(v.w)
                 : "memory");
}

// ---------------------------------------------------------------------------
// fp32 -> bf16 hi/lo split (vectorized x4)
// ---------------------------------------------------------------------------
__global__ void k_split(const float* __restrict__ src,
                        __nv_bfloat16* __restrict__ hi,
                        __nv_bfloat16* __restrict__ lo, int n4)
{
    int i = blockIdx.x * blockDim.x + threadIdx.x;
    if (i >= n4) return;
    float4 v = reinterpret_cast<const float4*>(src)[i];
    __nv_bfloat16 h0 = __float2bfloat16(v.x), h1 = __float2bfloat16(v.y);
    __nv_bfloat16 h2 = __float2bfloat16(v.z), h3 = __float2bfloat16(v.w);
    __nv_bfloat162 ph0; ph0.x = h0; ph0.y = h1;
    __nv_bfloat162 ph1; ph1.x = h2; ph1.y = h3;
    __nv_bfloat162 pl0, pl1;
    pl0.x = __float2bfloat16(v.x - __bfloat162float(h0));
    pl0.y = __float2bfloat16(v.y - __bfloat162float(h1));
    pl1.x = __float2bfloat16(v.z - __bfloat162float(h2));
    pl1.y = __float2bfloat16(v.w - __bfloat162float(h3));
    reinterpret_cast<__nv_bfloat162*>(hi)[i * 2]     = ph0;
    reinterpret_cast<__nv_bfloat162*>(hi)[i * 2 + 1] = ph1;
    reinterpret_cast<__nv_bfloat162*>(lo)[i * 2]     = pl0;
    reinterpret_cast<__nv_bfloat162*>(lo)[i * 2 + 1] = pl1;
}

// ---------------------------------------------------------------------------
// weight prep: transpose [k][n] -> [n][k], split to bf16 hi/lo. 8 units.
// ---------------------------------------------------------------------------
struct WSrc { const float* p[8]; };

__global__ void k_wprep(WSrc w,
                        __nv_bfloat16* __restrict__ oh,
                        __nv_bfloat16* __restrict__ ol)
{
    int u = blockIdx.y;
    int i = blockIdx.x * 256 + threadIdx.x;    // 0..16383 = n*128 + k
    int n = i >> 7, k = i & 127;
    float v = w.p[u][(size_t)k * DH + n];
    __nv_bfloat16 h = __float2bfloat16(v);
    oh[(size_t)u * 16384 + i] = h;
    ol[(size_t)u * 16384 + i] = __float2bfloat16(v - __bfloat162float(h));
}

// ---------------------------------------------------------------------------
// mma.sync bf16 GEMM with error-compensated split:
//   C[128-tile, 128] = sum_phases (A_h+A_l) @ (W_h+W_l)^T   (3 MMA terms)
// A given hi/lo [m][k]; W given hi/lo transposed [n][k] (= col-major for mma).
// Writes optional fp32 C (row stride ldc) and bf16 hi/lo split of C.
// 256 threads, 8 warps, warp tile 32x64.
// ---------------------------------------------------------------------------
__global__ __launch_bounds__(256)
void k_gemm_mma(const __nv_bfloat16* __restrict__ a0h, const __nv_bfloat16* __restrict__ a0l,
                const __nv_bfloat16* __restrict__ w0h, const __nv_bfloat16* __restrict__ w0l,
                const __nv_bfloat16* __restrict__ a1h, const __nv_bfloat16* __restrict__ a1l,
                const __nv_bfloat16* __restrict__ w1h, const __nv_bfloat16* __restrict__ w1l,
                const float* __restrict__ bias,
                float* __restrict__ cf,
                __nv_bfloat16* __restrict__ chi, __nv_bfloat16* __restrict__ clo,
                int M, int ldc, int relu)
{
    extern __shared__ __nv_bfloat16 sm[];
    __nv_bfloat16* sAh = sm;
    __nv_bfloat16* sAl = sAh + 128 * PADK;
    __nv_bfloat16* sBh = sAl + 128 * PADK;
    __nv_bfloat16* sBl = sBh + 128 * PADK;

    const int tid  = threadIdx.x;
    const int wid  = tid >> 5;
    const int lane = tid & 31;
    const int m0   = blockIdx.x * MTILE;
    const int wm   = (wid >> 1) * 32;   // warp row offset in tile
    const int wn   = (wid & 1) * 64;    // warp col offset in tile

    const uint32_t uAh = smem_to_u32(sAh);
    const uint32_t uAl = smem_to_u32(sAl);
    const uint32_t uBh = smem_to_u32(sBh);
    const uint32_t uBl = smem_to_u32(sBl);

    float acc[2][8][4];
#pragma unroll
    for (int mi = 0; mi < 2; ++mi)
#pragma unroll
        for (int ni = 0; ni < 8; ++ni)
#pragma unroll
            for (int q = 0; q < 4; ++q) acc[mi][ni][q] = 0.f;

#pragma unroll 1
    for (int phase = 0; phase < 2; ++phase) {
        const __nv_bfloat16* Ah = phase ? a1h : a0h;
        const __nv_bfloat16* Al = phase ? a1l : a0l;
        const __nv_bfloat16* Wh = phase ? w1h : w0h;
        const __nv_bfloat16* Wl = phase ? w1l : w0l;
        if (Ah == nullptr) break;

        __syncthreads();   // previous-phase reads done before overwrite
#pragma unroll
        for (int it = 0; it < 8; ++it) {
            int idx = tid + it * 256;          // 0..2047 uint4 slots
            int row = idx >> 4;                // 0..127
            int c8  = (idx & 15) << 3;         // 0..120
            size_t soff = (size_t)row * PADK + c8;
            uint4 vh = make_uint4(0, 0, 0, 0), vl = vh;
            if (m0 + row < M) {
                vh = *reinterpret_cast<const uint4*>(Ah + (size_t)(m0 + row) * DH + c8);
                vl = *reinterpret_cast<const uint4*>(Al + (size_t)(m0 + row) * DH + c8);
            }
            *reinterpret_cast<uint4*>(sAh + soff) = vh;
            *reinterpret_cast<uint4*>(sAl + soff) = vl;
            *reinterpret_cast<uint4*>(sBh + soff) =
                *reinterpret_cast<const uint4*>(Wh + (size_t)row * DH + c8);
            *reinterpret_cast<uint4*>(sBl + soff) =
                *reinterpret_cast<const uint4*>(Wl + (size_t)row * DH + c8);
        }
        __syncthreads();

#pragma unroll 1
        for (int kc = 0; kc < 8; ++kc) {
            int k0 = kc * 16;
            // A fragments (rows wm..wm+31): lane -> row (lane&15), k half (lane>>4)
            uint32_t a_off = (uint32_t)(((wm + (lane & 15)) * PADK + k0 + (lane >> 4) * 8) * 2);
            uint32_t ah[2][4], al[2][4];
            ldsm_x4(ah[0], uAh + a_off);
            ldsm_x4(ah[1], uAh + a_off + (uint32_t)(16 * PADK * 2));
            ldsm_x4(al[0], uAl + a_off);
            ldsm_x4(al[1], uAl + a_off + (uint32_t)(16 * PADK * 2));
            // B fragments: lane -> n row (lane&7), k half ((lane>>3)&1)
            uint32_t b_off = (uint32_t)(((wn + (lane & 7)) * PADK + k0 + ((lane >> 3) & 1) * 8) * 2);
            uint32_t bh[8][2], bl[8][2];
#pragma unroll
            for (int ni = 0; ni < 8; ++ni) {
                uint32_t o = b_off + (uint32_t)(ni * 8 * PADK * 2);
                ldsm_x2(bh[ni], uBh + o);
                ldsm_x2(bl[ni], uBl + o);
            }
#pragma unroll
            for (int mi = 0; mi < 2; ++mi)
#pragma unroll
                for (int ni = 0; ni < 8; ++ni) {
                    mma16816(acc[mi][ni], ah[mi], bh[ni]);
                    mma16816(acc[mi][ni], ah[mi], bl[ni]);
                    mma16816(acc[mi][ni], al[mi], bh[ni]);
                }
        }
    }

    // Epilogue straight from fragments.
    // c0,c1 -> (row = wm+mi*16+gid, col = wn+ni*8+tig*2), c2,c3 -> row+8.
    const int gid = lane >> 2, tig = lane & 3;
#pragma unroll
    for (int mi = 0; mi < 2; ++mi) {
#pragma unroll
        for (int half = 0; half < 2; ++half) {
            int r = wm + mi * 16 + gid + half * 8;
            int m = m0 + r;
            if (m >= M) continue;
#pragma unroll
            for (int ni = 0; ni < 8; ++ni) {
                int col = wn + ni * 8 + tig * 2;
                float v0 = acc[mi][ni][half * 2];
                float v1 = acc[mi][ni][half * 2 + 1];
                if (bias) { v0 += bias[col]; v1 += bias[col + 1]; }
                if (relu) { v0 = fmaxf(v0, 0.f); v1 = fmaxf(v1, 0.f); }
                if (cf)
                    *reinterpret_cast<float2*>(cf + (size_t)m * ldc + col) = make_float2(v0, v1);
                if (chi) {
                    __nv_bfloat16 h0 = __float2bfloat16(v0);
                    __nv_bfloat16 h1 = __float2bfloat16(v1);
                    __nv_bfloat162 ph; ph.x = h0; ph.y = h1;
                    __nv_bfloat162 pl;
                    pl.x = __float2bfloat16(v0 - __bfloat162float(h0));
                    pl.y = __float2bfloat16(v1 - __bfloat162float(h1));
                    *reinterpret_cast<__nv_bfloat162*>(chi + (size_t)m * DH + col) = ph;
                    *reinterpret_cast<__nv_bfloat162*>(clo + (size_t)m * DH + col) = pl;
                }
            }
        }
    }
}

// ---------------------------------------------------------------------------
// Edge head: warp per edge
// ---------------------------------------------------------------------------
__global__ __launch_bounds__(256)
void k_edge(const int* __restrict__ ei,
            const float* __restrict__ S,
            const float* __restrict__ bm1, const float* __restrict__ Wm2,
            const float* __restrict__ bm2,
            const float* __restrict__ bv1, const float* __restrict__ Wv2,
            const float* __restrict__ bv2,
            float* __restrict__ outMean, float* __restrict__ outVar, int E)
{
    int g = blockIdx.x * blockDim.x + threadIdx.x;
    int e = g >> 5, lane = g & 31;
    if (e >= E) return;

    float4 c_bm1 = *reinterpret_cast<const float4*>(&bm1[lane * 4]);
    float4 c_wm2 = *reinterpret_cast<const float4*>(&Wm2[lane * 4]);
    float4 c_bv1 = *reinterpret_cast<const float4*>(&bv1[lane * 4]);
    float4 c_wv2 = *reinterpret_cast<const float4*>(&Wv2[lane * 4]);

    int s = ei[e];
    int d = ei[(size_t)E + e];
    const float* Sp = S + (size_t)s * 512;
    const float* Dp = S + (size_t)d * 512;

    float4 am = *reinterpret_cast<const float4*>(&Sp[lane * 4]);
    float4 cv = *reinterpret_cast<const float4*>(&Sp[128 + lane * 4]);
    float4 bm = *reinterpret_cast<const float4*>(&Dp[256 + lane * 4]);
    float4 dv = *reinterpret_cast<const float4*>(&Dp[384 + lane * 4]);

    float pm = fmaxf(am.x + bm.x + c_bm1.x, 0.f) * c_wm2.x
             + fmaxf(am.y + bm.y + c_bm1.y, 0.f) * c_wm2.y
             + fmaxf(am.z + bm.z + c_bm1.z, 0.f) * c_wm2.z
             + fmaxf(am.w + bm.w + c_bm1.w, 0.f) * c_wm2.w;
    float pv = fmaxf(cv.x + dv.x + c_bv1.x, 0.f) * c_wv2.x
             + fmaxf(cv.y + dv.y + c_bv1.y, 0.f) * c_wv2.y
             + fmaxf(cv.z + dv.z + c_bv1.z, 0.f) * c_wv2.z
             + fmaxf(cv.w + dv.w + c_bv1.w, 0.f) * c_wv2.w;

#pragma unroll
    for (int off = 16; off > 0; off >>= 1) {
        pm += __shfl_xor_sync(0xFFFFFFFFu, pm, off);
        pv += __shfl_xor_sync(0xFFFFFFFFu, pv, off);
    }
    if (lane == 0) {
        outMean[e] = pm + bm2[0];
        outVar[e]  = expf(0.5f * (pv + bv2[0]));
    }
}

// ---------------------------------------------------------------------------
// kernel_launch
// ---------------------------------------------------------------------------
extern "C" void kernel_launch(void* const* d_in, const int* in_sizes, int n_in,
                              void* d_out, int out_size)
{
    const float* x       = (const float*)d_in[0];
    const int*   ei      = (const int*)d_in[1];
    const float* W1_rel  = (const float*)d_in[2];
    const float* b1      = (const float*)d_in[3];
    const float* W1_root = (const float*)d_in[4];
    const float* W2_rel  = (const float*)d_in[5];
    const float* b2      = (const float*)d_in[6];
    const float* W2_root = (const float*)d_in[7];
    const float* Wm1     = (const float*)d_in[8];
    const float* bm1     = (const float*)d_in[9];
    const float* Wm2     = (const float*)d_in[10];
    const float* bm2     = (const float*)d_in[11];
    const float* Wv1     = (const float*)d_in[12];
    const float* bv1     = (const float*)d_in[13];
    const float* Wv2     = (const float*)d_in[14];
    const float* bv2     = (const float*)d_in[15];

    int N = in_sizes[0] / DH;     // 50000
    int E = in_sizes[1] / 2;      // 800000
    float* out   = (float*)d_out;
    int    Ehalf = out_size / 2;

    float *agg, *h1, *S;
    __nv_bfloat16 *xh, *xl, *aggh, *aggl, *h1h, *h1l, *h2h, *h2l, *Wh, *Wl;
    cudaGetSymbolAddress((void**)&agg,  g_agg);
    cudaGetSymbolAddress((void**)&h1,   g_h1);
    cudaGetSymbolAddress((void**)&S,    g_S);
    cudaGetSymbolAddress((void**)&xh,   g_xh);
    cudaGetSymbolAddress((void**)&xl,   g_xl);
    cudaGetSymbolAddress((void**)&aggh, g_aggh);
    cudaGetSymbolAddress((void**)&aggl, g_aggl);
    cudaGetSymbolAddress((void**)&h1h,  g_h1h);
    cudaGetSymbolAddress((void**)&h1l,  g_h1l);
    cudaGetSymbolAddress((void**)&h2h,  g_h2h);
    cudaGetSymbolAddress((void**)&h2l,  g_h2l);
    cudaGetSymbolAddress((void**)&Wh,   g_Wh);
    cudaGetSymbolAddress((void**)&Wl,   g_Wl);

    const int DYN_SMEM = 4 * 128 * PADK * 2;   // 139264 B
    static int smem_set = 0;
    if (!smem_set) {
        cudaFuncSetAttribute(k_gemm_mma, cudaFuncAttributeMaxDynamicSharedMemorySize, DYN_SMEM);
        smem_set = 1;
    }

    int zeroB    = (N * (DH / 4) + 255) / 256;
    int scatterB = (E * 32 + 255) / 256;
    int splitB   = (N * (DH / 4) + 255) / 256;
    int gemmB    = (N + MTILE - 1) / MTILE;
    int edgeB    = (E * 32 + 255) / 256;
    int n4       = N * (DH / 4);

    // Weight prep
    WSrc ws;
    ws.p[0] = W1_rel;  ws.p[1] = W1_root;
    ws.p[2] = W2_rel;  ws.p[3] = W2_root;
    ws.p[4] = Wm1;     ws.p[5] = Wv1;
    ws.p[6] = Wm1 + 128 * DH;  ws.p[7] = Wv1 + 128 * DH;
    k_wprep<<<dim3(64, 8), 256>>>(ws, Wh, Wl);
    k_split<<<splitB, 256>>>(x, xh, xl, n4);

    // Layer 1
    k_zero<<<zeroB, 256>>>(agg, n4);
    k_scatter<<<scatterB, 256>>>(x, ei, E, agg);
    k_split<<<splitB, 256>>>(agg, aggh, aggl, n4);
    k_gemm_mma<<<gemmB, 256, DYN_SMEM>>>(aggh, aggl, Wh + 0 * 16384, Wl + 0 * 16384,
                                         xh, xl,     Wh + 1 * 16384, Wl + 1 * 16384,
                                         b1, h1, h1h, h1l, N, DH, 1);

    // Layer 2
    k_zero<<<zeroB, 256>>>(agg, n4);
    k_scatter<<<scatterB, 256>>>(h1, ei, E, agg);
    k_split<<<splitB, 256>>>(agg, aggh, aggl, n4);
    k_gemm_mma<<<gemmB, 256, DYN_SMEM>>>(aggh, aggl, Wh + 2 * 16384, Wl + 2 * 16384,
                                         h1h, h1l,   Wh + 3 * 16384, Wl + 3 * 16384,
                                         b2, nullptr, h2h, h2l, N, DH, 1);

    // Head node tables: S[n] = [Am | Cv | Bm | Dv]
    k_gemm_mma<<<gemmB, 256, DYN_SMEM>>>(h2h, h2l, Wh + 4 * 16384, Wl + 4 * 16384,
                                         nullptr, nullptr, nullptr, nullptr,
                                         nullptr, S + 0,   nullptr, nullptr, N, 512, 0);
    k_gemm_mma<<<gemmB, 256, DYN_SMEM>>>(h2h, h2l, Wh + 5 * 16384, Wl + 5 * 16384,
                                         nullptr, nullptr, nullptr, nullptr,
                                         nullptr, S + 128, nullptr, nullptr, N, 512, 0);
    k_gemm_mma<<<gemmB, 256, DYN_SMEM>>>(h2h, h2l, Wh + 6 * 16384, Wl + 6 * 16384,
                                         nullptr, nullptr, nullptr, nullptr,
                                         nullptr, S + 256, nullptr, nullptr, N, 512, 0);
    k_gemm_mma<<<gemmB, 256, DYN_SMEM>>>(h2h, h2l, Wh + 7 * 16384, Wl + 7 * 16384,
                                         nullptr, nullptr, nullptr, nullptr,
                                         nullptr, S + 384, nullptr, nullptr, N, 512, 0);

    // Edge heads
    k_edge<<<edgeB, 256>>>(ei, S, bm1, Wm2, bm2, bv1, Wv2, bv2,
                           out, out + Ehalf, E);
}

// round 11
// speedup vs baseline: 1.5781x; 1.1077x over previous
#include <cuda_runtime.h>
#include <cuda_bf16.h>
#include <cuda_fp16.h>
#include <math.h>
#include <stdint.h>

#define NMAX 50000
#define DH   128
#define MTILE 128
#define PADK 136      // bf16 elements per padded SMEM row (272 B)

// ---------------------------------------------------------------------------
// Scratch (__device__ globals; allocation-free rule)
// ---------------------------------------------------------------------------
__device__ float g_agg[(size_t)NMAX * DH];
__device__ float g_h1 [(size_t)NMAX * DH];
__device__ __half g_S [(size_t)NMAX * 512];   // fp16 [Am|Cv|Bm|Dv] per node

__device__ __nv_bfloat16 g_h1h [(size_t)NMAX * DH];
__device__ __nv_bfloat16 g_h1l [(size_t)NMAX * DH];
__device__ __nv_bfloat16 g_h2h [(size_t)NMAX * DH];
__device__ __nv_bfloat16 g_h2l [(size_t)NMAX * DH];
// 8 weight units, each transposed [n][k] 128x128, hi/lo
__device__ __nv_bfloat16 g_Wh[8 * 128 * 128];
__device__ __nv_bfloat16 g_Wl[8 * 128 * 128];

// ---------------------------------------------------------------------------
// helpers
// ---------------------------------------------------------------------------
__device__ __forceinline__ uint32_t smem_to_u32(const void* p) {
    uint32_t a;
    asm("{ .reg .u64 t; cvta.to.shared.u64 t, %1; cvt.u32.u64 %0, t; }"
        : "=r"(a) : "l"(p));
    return a;
}
__device__ __forceinline__ void ldsm_x4(uint32_t* r, uint32_t addr) {
    asm volatile("ldmatrix.sync.aligned.m8n8.x4.shared.b16 {%0,%1,%2,%3}, [%4];"
                 : "=r"(r[0]), "=r"(r[1]), "=r"(r[2]), "=r"(r[3]) : "r"(addr));
}
__device__ __forceinline__ void ldsm_x2(uint32_t* r, uint32_t addr) {
    asm volatile("ldmatrix.sync.aligned.m8n8.x2.shared.b16 {%0,%1}, [%2];"
                 : "=r"(r[0]), "=r"(r[1]) : "r"(addr));
}
__device__ __forceinline__ void mma16816(float* c, const uint32_t* a, const uint32_t* b) {
    asm volatile(
        "mma.sync.aligned.m16n8k16.row.col.f32.bf16.bf16.f32 "
        "{%0,%1,%2,%3}, {%4,%5,%6,%7}, {%8,%9}, {%0,%1,%2,%3};"
        : "+f"(c[0]), "+f"(c[1]), "+f"(c[2]), "+f"(c[3])
        : "r"(a[0]), "r"(a[1]), "r"(a[2]), "r"(a[3]), "r"(b[0]), "r"(b[1]));
}
// pack 2 floats -> bf16 hi pair + lo (residual) pair, as uint32 each
__device__ __forceinline__ void split2(float v0, float v1, uint32_t& hi, uint32_t& lo)
{
    __nv_bfloat162 h;
    h.x = __float2bfloat16(v0);
    h.y = __float2bfloat16(v1);
    __nv_bfloat162 l;
    l.x = __float2bfloat16(v0 - __bfloat162float(h.x));
    l.y = __float2bfloat16(v1 - __bfloat162float(h.y));
    hi = *reinterpret_cast<uint32_t*>(&h);
    lo = *reinterpret_cast<uint32_t*>(&l);
}

// ---------------------------------------------------------------------------
// zero kernel (float4)
// ---------------------------------------------------------------------------
__global__ void k_zero(float* __restrict__ p, int n4)
{
    int i = blockIdx.x * blockDim.x + threadIdx.x;
    if (i < n4) reinterpret_cast<float4*>(p)[i] = make_float4(0.f, 0.f, 0.f, 0.f);
}

// ---------------------------------------------------------------------------
// scatter: agg[dst] += feat[src], warp per edge, float4 per lane, vector RED
// ---------------------------------------------------------------------------
__global__ void k_scatter(const float* __restrict__ feat,
                          const int* __restrict__ ei,
                          int E, float* __restrict__ agg)
{
    int g = blockIdx.x * blockDim.x + threadIdx.x;
    int e = g >> 5, lane = g & 31;
    if (e >= E) return;
    int s = ei[e];
    int d = ei[(size_t)E + e];
    float4 v = *reinterpret_cast<const float4*>(&feat[(size_t)s * DH + lane * 4]);
    float* dst = &agg[(size_t)d * DH + lane * 4];
    asm volatile("red.global.add.v4.f32 [%0], {%1, %2, %3, %4};"
                 :: "l"(dst), "f"(v.x), "f"(v.y), "f"(v.z), "f"(v.w)
                 : "memory");
}

// ---------------------------------------------------------------------------
// weight prep: transpose [k][n] -> [n][k], split to bf16 hi/lo. 8 units.
// ---------------------------------------------------------------------------
struct WSrc { const float* p[8]; };

__global__ void k_wprep(WSrc w,
                        __nv_bfloat16* __restrict__ oh,
                        __nv_bfloat16* __restrict__ ol)
{
    int u = blockIdx.y;
    int i = blockIdx.x * 256 + threadIdx.x;    // 0..16383 = n*128 + k
    int n = i >> 7, k = i & 127;
    float v = w.p[u][(size_t)k * DH + n];
    __nv_bfloat16 h = __float2bfloat16(v);
    oh[(size_t)u * 16384 + i] = h;
    ol[(size_t)u * 16384 + i] = __float2bfloat16(v - __bfloat162float(h));
}

// ---------------------------------------------------------------------------
// mma.sync bf16 GEMM with error-compensated split (hi*hi + hi*lo + lo*hi):
// A per phase given either as fp32 (split fused into SMEM fill) or bf16 hi/lo.
// W given hi/lo transposed [n][k]. 256 threads, 8 warps, warp tile 32x64.
// ---------------------------------------------------------------------------
__global__ __launch_bounds__(256)
void k_gemm_mma(const float* __restrict__ a0f,
                const __nv_bfloat16* __restrict__ a0h, const __nv_bfloat16* __restrict__ a0l,
                const __nv_bfloat16* __restrict__ w0h, const __nv_bfloat16* __restrict__ w0l,
                const float* __restrict__ a1f,
                const __nv_bfloat16* __restrict__ a1h, const __nv_bfloat16* __restrict__ a1l,
                const __nv_bfloat16* __restrict__ w1h, const __nv_bfloat16* __restrict__ w1l,
                const float* __restrict__ bias,
                float* __restrict__ cf,
                __nv_bfloat16* __restrict__ chi, __nv_bfloat16* __restrict__ clo,
                int M, int relu)
{
    extern __shared__ __nv_bfloat16 sm[];
    __nv_bfloat16* sAh = sm;
    __nv_bfloat16* sAl = sAh + 128 * PADK;
    __nv_bfloat16* sBh = sAl + 128 * PADK;
    __nv_bfloat16* sBl = sBh + 128 * PADK;

    const int tid  = threadIdx.x;
    const int wid  = tid >> 5;
    const int lane = tid & 31;
    const int m0   = blockIdx.x * MTILE;
    const int wm   = (wid >> 1) * 32;
    const int wn   = (wid & 1) * 64;

    const uint32_t uAh = smem_to_u32(sAh);
    const uint32_t uAl = smem_to_u32(sAl);
    const uint32_t uBh = smem_to_u32(sBh);
    const uint32_t uBl = smem_to_u32(sBl);

    float acc[2][8][4];
#pragma unroll
    for (int mi = 0; mi < 2; ++mi)
#pragma unroll
        for (int ni = 0; ni < 8; ++ni)
#pragma unroll
            for (int q = 0; q < 4; ++q) acc[mi][ni][q] = 0.f;

#pragma unroll 1
    for (int phase = 0; phase < 2; ++phase) {
        const float*         Af = phase ? a1f : a0f;
        const __nv_bfloat16* Ah = phase ? a1h : a0h;
        const __nv_bfloat16* Al = phase ? a1l : a0l;
        const __nv_bfloat16* Wh = phase ? w1h : w0h;
        const __nv_bfloat16* Wl = phase ? w1l : w0l;
        if (Af == nullptr && Ah == nullptr) break;

        __syncthreads();
#pragma unroll
        for (int it = 0; it < 8; ++it) {
            int idx = tid + it * 256;          // 0..2047 uint4 slots
            int row = idx >> 4;                // 0..127
            int c8  = (idx & 15) << 3;         // 0..120
            size_t soff = (size_t)row * PADK + c8;
            uint4 vh = make_uint4(0, 0, 0, 0), vl = vh;
            if (m0 + row < M) {
                if (Af) {
                    const float* ap = Af + (size_t)(m0 + row) * DH + c8;
                    float4 f0 = *reinterpret_cast<const float4*>(ap);
                    float4 f1 = *reinterpret_cast<const float4*>(ap + 4);
                    split2(f0.x, f0.y, vh.x, vl.x);
                    split2(f0.z, f0.w, vh.y, vl.y);
                    split2(f1.x, f1.y, vh.z, vl.z);
                    split2(f1.z, f1.w, vh.w, vl.w);
                } else {
                    vh = *reinterpret_cast<const uint4*>(Ah + (size_t)(m0 + row) * DH + c8);
                    vl = *reinterpret_cast<const uint4*>(Al + (size_t)(m0 + row) * DH + c8);
                }
            }
            *reinterpret_cast<uint4*>(sAh + soff) = vh;
            *reinterpret_cast<uint4*>(sAl + soff) = vl;
            *reinterpret_cast<uint4*>(sBh + soff) =
                *reinterpret_cast<const uint4*>(Wh + (size_t)row * DH + c8);
            *reinterpret_cast<uint4*>(sBl + soff) =
                *reinterpret_cast<const uint4*>(Wl + (size_t)row * DH + c8);
        }
        __syncthreads();

#pragma unroll 1
        for (int kc = 0; kc < 8; ++kc) {
            int k0 = kc * 16;
            uint32_t a_off = (uint32_t)(((wm + (lane & 15)) * PADK + k0 + (lane >> 4) * 8) * 2);
            uint32_t ah[2][4], al[2][4];
            ldsm_x4(ah[0], uAh + a_off);
            ldsm_x4(ah[1], uAh + a_off + (uint32_t)(16 * PADK * 2));
            ldsm_x4(al[0], uAl + a_off);
            ldsm_x4(al[1], uAl + a_off + (uint32_t)(16 * PADK * 2));
            uint32_t b_off = (uint32_t)(((wn + (lane & 7)) * PADK + k0 + ((lane >> 3) & 1) * 8) * 2);
            uint32_t bh[8][2], bl[8][2];
#pragma unroll
            for (int ni = 0; ni < 8; ++ni) {
                uint32_t o = b_off + (uint32_t)(ni * 8 * PADK * 2);
                ldsm_x2(bh[ni], uBh + o);
                ldsm_x2(bl[ni], uBl + o);
            }
#pragma unroll
            for (int mi = 0; mi < 2; ++mi)
#pragma unroll
                for (int ni = 0; ni < 8; ++ni) {
                    mma16816(acc[mi][ni], ah[mi], bh[ni]);
                    mma16816(acc[mi][ni], ah[mi], bl[ni]);
                    mma16816(acc[mi][ni], al[mi], bh[ni]);
                }
        }
    }

    const int gid = lane >> 2, tig = lane & 3;
#pragma unroll
    for (int mi = 0; mi < 2; ++mi) {
#pragma unroll
        for (int half = 0; half < 2; ++half) {
            int r = wm + mi * 16 + gid + half * 8;
            int m = m0 + r;
            if (m >= M) continue;
#pragma unroll
            for (int ni = 0; ni < 8; ++ni) {
                int col = wn + ni * 8 + tig * 2;
                float v0 = acc[mi][ni][half * 2];
                float v1 = acc[mi][ni][half * 2 + 1];
                if (bias) { v0 += bias[col]; v1 += bias[col + 1]; }
                if (relu) { v0 = fmaxf(v0, 0.f); v1 = fmaxf(v1, 0.f); }
                if (cf)
                    *reinterpret_cast<float2*>(cf + (size_t)m * DH + col) = make_float2(v0, v1);
                if (chi) {
                    uint32_t ph, pl;
                    split2(v0, v1, ph, pl);
                    *reinterpret_cast<uint32_t*>(chi + (size_t)m * DH + col) = ph;
                    *reinterpret_cast<uint32_t*>(clo + (size_t)m * DH + col) = pl;
                }
            }
        }
    }
}

// ---------------------------------------------------------------------------
// Merged head GEMM: A = h2 (bf16 hi/lo) loaded to SMEM ONCE; loop 4 weight
// units (Wm1_top, Wv1_top, Wm1_bot, Wv1_bot at +u*16384); write fp16 S
// segments [Am|Cv|Bm|Dv] at S[m*512 + u*128 + col].
// ---------------------------------------------------------------------------
__global__ __launch_bounds__(256)
void k_gemm_head(const __nv_bfloat16* __restrict__ ah_, const __nv_bfloat16* __restrict__ al_,
                 const __nv_bfloat16* __restrict__ Wh4, const __nv_bfloat16* __restrict__ Wl4,
                 __half* __restrict__ S, int M)
{
    extern __shared__ __nv_bfloat16 sm[];
    __nv_bfloat16* sAh = sm;
    __nv_bfloat16* sAl = sAh + 128 * PADK;
    __nv_bfloat16* sBh = sAl + 128 * PADK;
    __nv_bfloat16* sBl = sBh + 128 * PADK;

    const int tid  = threadIdx.x;
    const int wid  = tid >> 5;
    const int lane = tid & 31;
    const int m0   = blockIdx.x * MTILE;
    const int wm   = (wid >> 1) * 32;
    const int wn   = (wid & 1) * 64;

    const uint32_t uAh = smem_to_u32(sAh);
    const uint32_t uAl = smem_to_u32(sAl);
    const uint32_t uBh = smem_to_u32(sBh);
    const uint32_t uBl = smem_to_u32(sBl);

    // Fill A once
#pragma unroll
    for (int it = 0; it < 8; ++it) {
        int idx = tid + it * 256;
        int row = idx >> 4;
        int c8  = (idx & 15) << 3;
        size_t soff = (size_t)row * PADK + c8;
        uint4 vh = make_uint4(0, 0, 0, 0), vl = vh;
        if (m0 + row < M) {
            vh = *reinterpret_cast<const uint4*>(ah_ + (size_t)(m0 + row) * DH + c8);
            vl = *reinterpret_cast<const uint4*>(al_ + (size_t)(m0 + row) * DH + c8);
        }
        *reinterpret_cast<uint4*>(sAh + soff) = vh;
        *reinterpret_cast<uint4*>(sAl + soff) = vl;
    }

    const int gid = lane >> 2, tig = lane & 3;

#pragma unroll 1
    for (int u = 0; u < 4; ++u) {
        const __nv_bfloat16* Wh = Wh4 + (size_t)u * 16384;
        const __nv_bfloat16* Wl = Wl4 + (size_t)u * 16384;

        __syncthreads();   // prior unit's B reads done (also covers A fill on u=0)
#pragma unroll
        for (int it = 0; it < 8; ++it) {
            int idx = tid + it * 256;
            int row = idx >> 4;
            int c8  = (idx & 15) << 3;
            size_t soff = (size_t)row * PADK + c8;
            *reinterpret_cast<uint4*>(sBh + soff) =
                *reinterpret_cast<const uint4*>(Wh + (size_t)row * DH + c8);
            *reinterpret_cast<uint4*>(sBl + soff) =
                *reinterpret_cast<const uint4*>(Wl + (size_t)row * DH + c8);
        }
        __syncthreads();

        float acc[2][8][4];
#pragma unroll
        for (int mi = 0; mi < 2; ++mi)
#pragma unroll
            for (int ni = 0; ni < 8; ++ni)
#pragma unroll
                for (int q = 0; q < 4; ++q) acc[mi][ni][q] = 0.f;

#pragma unroll 1
        for (int kc = 0; kc < 8; ++kc) {
            int k0 = kc * 16;
            uint32_t a_off = (uint32_t)(((wm + (lane & 15)) * PADK + k0 + (lane >> 4) * 8) * 2);
            uint32_t ah[2][4], al[2][4];
            ldsm_x4(ah[0], uAh + a_off);
            ldsm_x4(ah[1], uAh + a_off + (uint32_t)(16 * PADK * 2));
            ldsm_x4(al[0], uAl + a_off);
            ldsm_x4(al[1], uAl + a_off + (uint32_t)(16 * PADK * 2));
            uint32_t b_off = (uint32_t)(((wn + (lane & 7)) * PADK + k0 + ((lane >> 3) & 1) * 8) * 2);
            uint32_t bh[8][2], bl[8][2];
#pragma unroll
            for (int ni = 0; ni < 8; ++ni) {
                uint32_t o = b_off + (uint32_t)(ni * 8 * PADK * 2);
                ldsm_x2(bh[ni], uBh + o);
                ldsm_x2(bl[ni], uBl + o);
            }
#pragma unroll
            for (int mi = 0; mi < 2; ++mi)
#pragma unroll
                for (int ni = 0; ni < 8; ++ni) {
                    mma16816(acc[mi][ni], ah[mi], bh[ni]);
                    mma16816(acc[mi][ni], ah[mi], bl[ni]);
                    mma16816(acc[mi][ni], al[mi], bh[ni]);
                }
        }

        // Epilogue: fp16 write to S segment u
#pragma unroll
        for (int mi = 0; mi < 2; ++mi) {
#pragma unroll
            for (int half = 0; half < 2; ++half) {
                int r = wm + mi * 16 + gid + half * 8;
                int m = m0 + r;
                if (m >= M) continue;
#pragma unroll
                for (int ni = 0; ni < 8; ++ni) {
                    int col = wn + ni * 8 + tig * 2;
                    __half2 hv = __floats2half2_rn(acc[mi][ni][half * 2],
                                                   acc[mi][ni][half * 2 + 1]);
                    *reinterpret_cast<__half2*>(S + (size_t)m * 512 + u * 128 + col) = hv;
                }
            }
        }
    }
}

// ---------------------------------------------------------------------------
// Edge head: warp per edge, fp16 S table (1KB per edge instead of 2KB)
// ---------------------------------------------------------------------------
__global__ __launch_bounds__(256)
void k_edge(const int* __restrict__ ei,
            const __half* __restrict__ S,
            const float* __restrict__ bm1, const float* __restrict__ Wm2,
            const float* __restrict__ bm2,
            const float* __restrict__ bv1, const float* __restrict__ Wv2,
            const float* __restrict__ bv2,
            float* __restrict__ outMean, float* __restrict__ outVar, int E)
{
    int g = blockIdx.x * blockDim.x + threadIdx.x;
    int e = g >> 5, lane = g & 31;
    if (e >= E) return;

    float4 c_bm1 = *reinterpret_cast<const float4*>(&bm1[lane * 4]);
    float4 c_wm2 = *reinterpret_cast<const float4*>(&Wm2[lane * 4]);
    float4 c_bv1 = *reinterpret_cast<const float4*>(&bv1[lane * 4]);
    float4 c_wv2 = *reinterpret_cast<const float4*>(&Wv2[lane * 4]);

    int s = ei[e];
    int d = ei[(size_t)E + e];
    const __half* Sp = S + (size_t)s * 512;
    const __half* Dp = S + (size_t)d * 512;

    __half2 am2[2], cv2[2], bm2h[2], dv2[2];
    *reinterpret_cast<uint2*>(am2)  = *reinterpret_cast<const uint2*>(Sp + lane * 4);
    *reinterpret_cast<uint2*>(cv2)  = *reinterpret_cast<const uint2*>(Sp + 128 + lane * 4);
    *reinterpret_cast<uint2*>(bm2h) = *reinterpret_cast<const uint2*>(Dp + 256 + lane * 4);
    *reinterpret_cast<uint2*>(dv2)  = *reinterpret_cast<const uint2*>(Dp + 384 + lane * 4);

    float2 am0 = __half22float2(am2[0]),  am1 = __half22float2(am2[1]);
    float2 cv0 = __half22float2(cv2[0]),  cv1 = __half22float2(cv2[1]);
    float2 bm0 = __half22float2(bm2h[0]), bm1f = __half22float2(bm2h[1]);
    float2 dv0 = __half22float2(dv2[0]),  dv1 = __half22float2(dv2[1]);

    float pm = fmaxf(am0.x + bm0.x + c_bm1.x, 0.f) * c_wm2.x
             + fmaxf(am0.y + bm0.y + c_bm1.y, 0.f) * c_wm2.y
             + fmaxf(am1.x + bm1f.x + c_bm1.z, 0.f) * c_wm2.z
             + fmaxf(am1.y + bm1f.y + c_bm1.w, 0.f) * c_wm2.w;
    float pv = fmaxf(cv0.x + dv0.x + c_bv1.x, 0.f) * c_wv2.x
             + fmaxf(cv0.y + dv0.y + c_bv1.y, 0.f) * c_wv2.y
             + fmaxf(cv1.x + dv1.x + c_bv1.z, 0.f) * c_wv2.z
             + fmaxf(cv1.y + dv1.y + c_bv1.w, 0.f) * c_wv2.w;

#pragma unroll
    for (int off = 16; off > 0; off >>= 1) {
        pm += __shfl_xor_sync(0xFFFFFFFFu, pm, off);
        pv += __shfl_xor_sync(0xFFFFFFFFu, pv, off);
    }
    if (lane == 0) {
        outMean[e] = pm + bm2[0];
        outVar[e]  = expf(0.5f * (pv + bv2[0]));
    }
}

// ---------------------------------------------------------------------------
// kernel_launch
// ---------------------------------------------------------------------------
extern "C" void kernel_launch(void* const* d_in, const int* in_sizes, int n_in,
                              void* d_out, int out_size)
{
    const float* x       = (const float*)d_in[0];
    const int*   ei      = (const int*)d_in[1];
    const float* W1_rel  = (const float*)d_in[2];
    const float* b1      = (const float*)d_in[3];
    const float* W1_root = (const float*)d_in[4];
    const float* W2_rel  = (const float*)d_in[5];
    const float* b2      = (const float*)d_in[6];
    const float* W2_root = (const float*)d_in[7];
    const float* Wm1     = (const float*)d_in[8];
    const float* bm1     = (const float*)d_in[9];
    const float* Wm2     = (const float*)d_in[10];
    const float* bm2     = (const float*)d_in[11];
    const float* Wv1     = (const float*)d_in[12];
    const float* bv1     = (const float*)d_in[13];
    const float* Wv2     = (const float*)d_in[14];
    const float* bv2     = (const float*)d_in[15];

    int N = in_sizes[0] / DH;     // 50000
    int E = in_sizes[1] / 2;      // 800000
    float* out   = (float*)d_out;
    int    Ehalf = out_size / 2;

    float *agg, *h1;
    __half* S;
    __nv_bfloat16 *h1h, *h1l, *h2h, *h2l, *Wh, *Wl;
    cudaGetSymbolAddress((void**)&agg,  g_agg);
    cudaGetSymbolAddress((void**)&h1,   g_h1);
    cudaGetSymbolAddress((void**)&S,    g_S);
    cudaGetSymbolAddress((void**)&h1h,  g_h1h);
    cudaGetSymbolAddress((void**)&h1l,  g_h1l);
    cudaGetSymbolAddress((void**)&h2h,  g_h2h);
    cudaGetSymbolAddress((void**)&h2l,  g_h2l);
    cudaGetSymbolAddress((void**)&Wh,   g_Wh);
    cudaGetSymbolAddress((void**)&Wl,   g_Wl);

    const int DYN_SMEM = 4 * 128 * PADK * 2;   // 139264 B
    static int smem_set = 0;
    if (!smem_set) {
        cudaFuncSetAttribute(k_gemm_mma,  cudaFuncAttributeMaxDynamicSharedMemorySize, DYN_SMEM);
        cudaFuncSetAttribute(k_gemm_head, cudaFuncAttributeMaxDynamicSharedMemorySize, DYN_SMEM);
        smem_set = 1;
    }

    int zeroB    = (N * (DH / 4) + 255) / 256;
    int scatterB = (E * 32 + 255) / 256;
    int gemmB    = (N + MTILE - 1) / MTILE;
    int edgeB    = (E * 32 + 255) / 256;
    int n4       = N * (DH / 4);

    // Weight prep
    WSrc ws;
    ws.p[0] = W1_rel;  ws.p[1] = W1_root;
    ws.p[2] = W2_rel;  ws.p[3] = W2_root;
    ws.p[4] = Wm1;     ws.p[5] = Wv1;
    ws.p[6] = Wm1 + 128 * DH;  ws.p[7] = Wv1 + 128 * DH;
    k_wprep<<<dim3(64, 8), 256>>>(ws, Wh, Wl);

    // Layer 1: agg@W1rel + x@W1root (both A inputs fp32, split fused in fill)
    k_zero<<<zeroB, 256>>>(agg, n4);
    k_scatter<<<scatterB, 256>>>(x, ei, E, agg);
    k_gemm_mma<<<gemmB, 256, DYN_SMEM>>>(
        agg, nullptr, nullptr, Wh + 0 * 16384, Wl + 0 * 16384,
        x,   nullptr, nullptr, Wh + 1 * 16384, Wl + 1 * 16384,
        b1, h1, h1h, h1l, N, 1);

    // Layer 2: agg(h1)@W2rel + h1@W2root (agg fp32 fused; h1 as bf16 hi/lo)
    k_zero<<<zeroB, 256>>>(agg, n4);
    k_scatter<<<scatterB, 256>>>(h1, ei, E, agg);
    k_gemm_mma<<<gemmB, 256, DYN_SMEM>>>(
        agg,     nullptr, nullptr, Wh + 2 * 16384, Wl + 2 * 16384,
        nullptr, h1h,     h1l,     Wh + 3 * 16384, Wl + 3 * 16384,
        b2, nullptr, h2h, h2l, N, 1);

    // Head node tables: one kernel, 4 units, fp16 S = [Am|Cv|Bm|Dv]
    k_gemm_head<<<gemmB, 256, DYN_SMEM>>>(h2h, h2l,
                                          Wh + 4 * 16384, Wl + 4 * 16384, S, N);

    // Edge heads
    k_edge<<<edgeB, 256>>>(ei, S, bm1, Wm2, bm2, bv1, Wv2, bv2,
                           out, out + Ehalf, E);
}

// round 12
// speedup vs baseline: 1.7557x; 1.1126x over previous
#include <cuda_runtime.h>
#include <cuda_bf16.h>
#include <cuda_fp16.h>
#include <math.h>
#include <stdint.h>

#define NMAX 50000
#define EMAX 800000
#define DH   128
#define MTILE 128
#define PADK 136      // bf16 elements per padded SMEM row (272 B)

// ---------------------------------------------------------------------------
// Scratch (__device__ globals; allocation-free rule)
// ---------------------------------------------------------------------------
__device__ float g_agg[(size_t)NMAX * DH];
__device__ float g_h1 [(size_t)NMAX * DH];
__device__ __half g_S [(size_t)NMAX * 512];   // fp16 [Am|Cv|Bm|Dv] per node

__device__ __nv_bfloat16 g_h1h [(size_t)NMAX * DH];
__device__ __nv_bfloat16 g_h1l [(size_t)NMAX * DH];
__device__ __nv_bfloat16 g_h2h [(size_t)NMAX * DH];
__device__ __nv_bfloat16 g_h2l [(size_t)NMAX * DH];
__device__ __nv_bfloat16 g_Wh[8 * 128 * 128];
__device__ __nv_bfloat16 g_Wl[8 * 128 * 128];

// CSR scratch
__device__ int g_deg   [NMAX + 64];
__device__ int g_off   [NMAX + 64];
__device__ int g_cursor[NMAX + 64];
__device__ int g_csr   [EMAX];

// ---------------------------------------------------------------------------
// helpers
// ---------------------------------------------------------------------------
__device__ __forceinline__ uint32_t smem_to_u32(const void* p) {
    uint32_t a;
    asm("{ .reg .u64 t; cvta.to.shared.u64 t, %1; cvt.u32.u64 %0, t; }"
        : "=r"(a) : "l"(p));
    return a;
}
__device__ __forceinline__ void ldsm_x4(uint32_t* r, uint32_t addr) {
    asm volatile("ldmatrix.sync.aligned.m8n8.x4.shared.b16 {%0,%1,%2,%3}, [%4];"
                 : "=r"(r[0]), "=r"(r[1]), "=r"(r[2]), "=r"(r[3]) : "r"(addr));
}
__device__ __forceinline__ void ldsm_x2(uint32_t* r, uint32_t addr) {
    asm volatile("ldmatrix.sync.aligned.m8n8.x2.shared.b16 {%0,%1}, [%2];"
                 : "=r"(r[0]), "=r"(r[1]) : "r"(addr));
}
__device__ __forceinline__ void mma16816(float* c, const uint32_t* a, const uint32_t* b) {
    asm volatile(
        "mma.sync.aligned.m16n8k16.row.col.f32.bf16.bf16.f32 "
        "{%0,%1,%2,%3}, {%4,%5,%6,%7}, {%8,%9}, {%0,%1,%2,%3};"
        : "+f"(c[0]), "+f"(c[1]), "+f"(c[2]), "+f"(c[3])
        : "r"(a[0]), "r"(a[1]), "r"(a[2]), "r"(a[3]), "r"(b[0]), "r"(b[1]));
}
__device__ __forceinline__ void split2(float v0, float v1, uint32_t& hi, uint32_t& lo)
{
    __nv_bfloat162 h;
    h.x = __float2bfloat16(v0);
    h.y = __float2bfloat16(v1);
    __nv_bfloat162 l;
    l.x = __float2bfloat16(v0 - __bfloat162float(h.x));
    l.y = __float2bfloat16(v1 - __bfloat162float(h.y));
    hi = *reinterpret_cast<uint32_t*>(&h);
    lo = *reinterpret_cast<uint32_t*>(&l);
}

// ---------------------------------------------------------------------------
// CSR build
// ---------------------------------------------------------------------------
__global__ void k_zeroi(int* __restrict__ p, int n)
{
    int i = blockIdx.x * blockDim.x + threadIdx.x;
    if (i < n) p[i] = 0;
}

__global__ void k_hist(const int* __restrict__ ei, int E, int* __restrict__ deg)
{
    int e = blockIdx.x * blockDim.x + threadIdx.x;
    if (e < E) atomicAdd(&deg[ei[(size_t)E + e]], 1);
}

// single-block exclusive scan over N degrees -> off, cursor; off[N] = total
__global__ void k_scan(const int* __restrict__ deg, int* __restrict__ off,
                       int* __restrict__ cursor, int N)
{
    __shared__ int part[1024];
    const int t = threadIdx.x;
    const int C = (N + 1023) / 1024;
    const int base = t * C;
    int s = 0;
    for (int j = 0; j < C; ++j) {
        int i = base + j;
        if (i < N) s += deg[i];
    }
    part[t] = s;
    __syncthreads();
    for (int d = 1; d < 1024; d <<= 1) {
        int v = (t >= d) ? part[t - d] : 0;
        __syncthreads();
        part[t] += v;
        __syncthreads();
    }
    int run = (t > 0) ? part[t - 1] : 0;
    for (int j = 0; j < C; ++j) {
        int i = base + j;
        if (i < N) {
            off[i] = run;
            cursor[i] = run;
            run += deg[i];
        }
    }
    if (t == 1023) off[N] = part[1023];
}

__global__ void k_fill(const int* __restrict__ ei, int E,
                       int* __restrict__ cursor, int* __restrict__ csr)
{
    int e = blockIdx.x * blockDim.x + threadIdx.x;
    if (e >= E) return;
    int s = ei[e];
    int d = ei[(size_t)E + e];
    int pos = atomicAdd(&cursor[d], 1);
    csr[pos] = s;
}

// ---------------------------------------------------------------------------
// gather-reduce: agg[n] = sum over edges (dst=n) of feat[src]; warp per node
// ---------------------------------------------------------------------------
__global__ void k_gather(const float* __restrict__ feat,
                         const int* __restrict__ csr, const int* __restrict__ off,
                         float* __restrict__ agg, int N)
{
    int g = blockIdx.x * blockDim.x + threadIdx.x;
    int n = g >> 5, lane = g & 31;
    if (n >= N) return;
    int s0 = off[n], s1 = off[n + 1];
    float4 acc = make_float4(0.f, 0.f, 0.f, 0.f);
    for (int base = s0; base < s1; base += 32) {
        int cnt = min(32, s1 - base);
        int idx = (base + lane < s1) ? csr[base + lane] : 0;
#pragma unroll 4
        for (int j = 0; j < cnt; ++j) {
            int s = __shfl_sync(0xFFFFFFFFu, idx, j);
            float4 v = *reinterpret_cast<const float4*>(&feat[(size_t)s * DH + lane * 4]);
            acc.x += v.x; acc.y += v.y; acc.z += v.z; acc.w += v.w;
        }
    }
    *reinterpret_cast<float4*>(&agg[(size_t)n * DH + lane * 4]) = acc;
}

// ---------------------------------------------------------------------------
// weight prep: transpose [k][n] -> [n][k], split to bf16 hi/lo. 8 units.
// ---------------------------------------------------------------------------
struct WSrc { const float* p[8]; };

__global__ void k_wprep(WSrc w,
                        __nv_bfloat16* __restrict__ oh,
                        __nv_bfloat16* __restrict__ ol)
{
    int u = blockIdx.y;
    int i = blockIdx.x * 256 + threadIdx.x;
    int n = i >> 7, k = i & 127;
    float v = w.p[u][(size_t)k * DH + n];
    __nv_bfloat16 h = __float2bfloat16(v);
    oh[(size_t)u * 16384 + i] = h;
    ol[(size_t)u * 16384 + i] = __float2bfloat16(v - __bfloat162float(h));
}

// ---------------------------------------------------------------------------
// mma.sync bf16 GEMM, error-compensated split (hi*hi + hi*lo + lo*hi).
// 512 threads, 16 warps, warp tile 16x64 (8 m-groups x 2 n-groups).
// ---------------------------------------------------------------------------
__global__ __launch_bounds__(512)
void k_gemm_mma(const float* __restrict__ a0f,
                const __nv_bfloat16* __restrict__ a0h, const __nv_bfloat16* __restrict__ a0l,
                const __nv_bfloat16* __restrict__ w0h, const __nv_bfloat16* __restrict__ w0l,
                const float* __restrict__ a1f,
                const __nv_bfloat16* __restrict__ a1h, const __nv_bfloat16* __restrict__ a1l,
                const __nv_bfloat16* __restrict__ w1h, const __nv_bfloat16* __restrict__ w1l,
                const float* __restrict__ bias,
                float* __restrict__ cf,
                __nv_bfloat16* __restrict__ chi, __nv_bfloat16* __restrict__ clo,
                int M, int relu)
{
    extern __shared__ __nv_bfloat16 sm[];
    __nv_bfloat16* sAh = sm;
    __nv_bfloat16* sAl = sAh + 128 * PADK;
    __nv_bfloat16* sBh = sAl + 128 * PADK;
    __nv_bfloat16* sBl = sBh + 128 * PADK;

    const int tid  = threadIdx.x;
    const int wid  = tid >> 5;
    const int lane = tid & 31;
    const int m0   = blockIdx.x * MTILE;
    const int wm   = (wid >> 1) * 16;
    const int wn   = (wid & 1) * 64;

    const uint32_t uAh = smem_to_u32(sAh);
    const uint32_t uAl = smem_to_u32(sAl);
    const uint32_t uBh = smem_to_u32(sBh);
    const uint32_t uBl = smem_to_u32(sBl);

    float acc[8][4];
#pragma unroll
    for (int ni = 0; ni < 8; ++ni)
#pragma unroll
        for (int q = 0; q < 4; ++q) acc[ni][q] = 0.f;

#pragma unroll 1
    for (int phase = 0; phase < 2; ++phase) {
        const float*         Af = phase ? a1f : a0f;
        const __nv_bfloat16* Ah = phase ? a1h : a0h;
        const __nv_bfloat16* Al = phase ? a1l : a0l;
        const __nv_bfloat16* Wh = phase ? w1h : w0h;
        const __nv_bfloat16* Wl = phase ? w1l : w0l;
        if (Af == nullptr && Ah == nullptr) break;

        __syncthreads();
#pragma unroll
        for (int it = 0; it < 4; ++it) {
            int idx = tid + it * 512;          // 0..2047 uint4 slots
            int row = idx >> 4;
            int c8  = (idx & 15) << 3;
            size_t soff = (size_t)row * PADK + c8;
            uint4 vh = make_uint4(0, 0, 0, 0), vl = vh;
            if (m0 + row < M) {
                if (Af) {
                    const float* ap = Af + (size_t)(m0 + row) * DH + c8;
                    float4 f0 = *reinterpret_cast<const float4*>(ap);
                    float4 f1 = *reinterpret_cast<const float4*>(ap + 4);
                    split2(f0.x, f0.y, vh.x, vl.x);
                    split2(f0.z, f0.w, vh.y, vl.y);
                    split2(f1.x, f1.y, vh.z, vl.z);
                    split2(f1.z, f1.w, vh.w, vl.w);
                } else {
                    vh = *reinterpret_cast<const uint4*>(Ah + (size_t)(m0 + row) * DH + c8);
                    vl = *reinterpret_cast<const uint4*>(Al + (size_t)(m0 + row) * DH + c8);
                }
            }
            *reinterpret_cast<uint4*>(sAh + soff) = vh;
            *reinterpret_cast<uint4*>(sAl + soff) = vl;
            *reinterpret_cast<uint4*>(sBh + soff) =
                *reinterpret_cast<const uint4*>(Wh + (size_t)row * DH + c8);
            *reinterpret_cast<uint4*>(sBl + soff) =
                *reinterpret_cast<const uint4*>(Wl + (size_t)row * DH + c8);
        }
        __syncthreads();

#pragma unroll 1
        for (int kc = 0; kc < 8; ++kc) {
            int k0 = kc * 16;
            uint32_t a_off = (uint32_t)(((wm + (lane & 15)) * PADK + k0 + (lane >> 4) * 8) * 2);
            uint32_t ah[4], al[4];
            ldsm_x4(ah, uAh + a_off);
            ldsm_x4(al, uAl + a_off);
            uint32_t b_off = (uint32_t)(((wn + (lane & 7)) * PADK + k0 + ((lane >> 3) & 1) * 8) * 2);
            uint32_t bh[8][2], bl[8][2];
#pragma unroll
            for (int ni = 0; ni < 8; ++ni) {
                uint32_t o = b_off + (uint32_t)(ni * 8 * PADK * 2);
                ldsm_x2(bh[ni], uBh + o);
                ldsm_x2(bl[ni], uBl + o);
            }
#pragma unroll
            for (int ni = 0; ni < 8; ++ni) {
                mma16816(acc[ni], ah, bh[ni]);
                mma16816(acc[ni], ah, bl[ni]);
                mma16816(acc[ni], al, bh[ni]);
            }
        }
    }

    const int gid = lane >> 2, tig = lane & 3;
#pragma unroll
    for (int half = 0; half < 2; ++half) {
        int r = wm + gid + half * 8;
        int m = m0 + r;
        if (m >= M) continue;
#pragma unroll
        for (int ni = 0; ni < 8; ++ni) {
            int col = wn + ni * 8 + tig * 2;
            float v0 = acc[ni][half * 2];
            float v1 = acc[ni][half * 2 + 1];
            if (bias) { v0 += bias[col]; v1 += bias[col + 1]; }
            if (relu) { v0 = fmaxf(v0, 0.f); v1 = fmaxf(v1, 0.f); }
            if (cf)
                *reinterpret_cast<float2*>(cf + (size_t)m * DH + col) = make_float2(v0, v1);
            if (chi) {
                uint32_t ph, pl;
                split2(v0, v1, ph, pl);
                *reinterpret_cast<uint32_t*>(chi + (size_t)m * DH + col) = ph;
                *reinterpret_cast<uint32_t*>(clo + (size_t)m * DH + col) = pl;
            }
        }
    }
}

// ---------------------------------------------------------------------------
// Merged head GEMM: A (h2 hi/lo) loaded once; 4 weight units; fp16 S out.
// 512 threads, 16 warps, warp tile 16x64.
// ---------------------------------------------------------------------------
__global__ __launch_bounds__(512)
void k_gemm_head(const __nv_bfloat16* __restrict__ ah_, const __nv_bfloat16* __restrict__ al_,
                 const __nv_bfloat16* __restrict__ Wh4, const __nv_bfloat16* __restrict__ Wl4,
                 __half* __restrict__ S, int M)
{
    extern __shared__ __nv_bfloat16 sm[];
    __nv_bfloat16* sAh = sm;
    __nv_bfloat16* sAl = sAh + 128 * PADK;
    __nv_bfloat16* sBh = sAl + 128 * PADK;
    __nv_bfloat16* sBl = sBh + 128 * PADK;

    const int tid  = threadIdx.x;
    const int wid  = tid >> 5;
    const int lane = tid & 31;
    const int m0   = blockIdx.x * MTILE;
    const int wm   = (wid >> 1) * 16;
    const int wn   = (wid & 1) * 64;

    const uint32_t uAh = smem_to_u32(sAh);
    const uint32_t uAl = smem_to_u32(sAl);
    const uint32_t uBh = smem_to_u32(sBh);
    const uint32_t uBl = smem_to_u32(sBl);

#pragma unroll
    for (int it = 0; it < 4; ++it) {
        int idx = tid + it * 512;
        int row = idx >> 4;
        int c8  = (idx & 15) << 3;
        size_t soff = (size_t)row * PADK + c8;
        uint4 vh = make_uint4(0, 0, 0, 0), vl = vh;
        if (m0 + row < M) {
            vh = *reinterpret_cast<const uint4*>(ah_ + (size_t)(m0 + row) * DH + c8);
            vl = *reinterpret_cast<const uint4*>(al_ + (size_t)(m0 + row) * DH + c8);
        }
        *reinterpret_cast<uint4*>(sAh + soff) = vh;
        *reinterpret_cast<uint4*>(sAl + soff) = vl;
    }

    const int gid = lane >> 2, tig = lane & 3;

#pragma unroll 1
    for (int u = 0; u < 4; ++u) {
        const __nv_bfloat16* Wh = Wh4 + (size_t)u * 16384;
        const __nv_bfloat16* Wl = Wl4 + (size_t)u * 16384;

        __syncthreads();
#pragma unroll
        for (int it = 0; it < 4; ++it) {
            int idx = tid + it * 512;
            int row = idx >> 4;
            int c8  = (idx & 15) << 3;
            size_t soff = (size_t)row * PADK + c8;
            *reinterpret_cast<uint4*>(sBh + soff) =
                *reinterpret_cast<const uint4*>(Wh + (size_t)row * DH + c8);
            *reinterpret_cast<uint4*>(sBl + soff) =
                *reinterpret_cast<const uint4*>(Wl + (size_t)row * DH + c8);
        }
        __syncthreads();

        float acc[8][4];
#pragma unroll
        for (int ni = 0; ni < 8; ++ni)
#pragma unroll
            for (int q = 0; q < 4; ++q) acc[ni][q] = 0.f;

#pragma unroll 1
        for (int kc = 0; kc < 8; ++kc) {
            int k0 = kc * 16;
            uint32_t a_off = (uint32_t)(((wm + (lane & 15)) * PADK + k0 + (lane >> 4) * 8) * 2);
            uint32_t ah[4], al[4];
            ldsm_x4(ah, uAh + a_off);
            ldsm_x4(al, uAl + a_off);
            uint32_t b_off = (uint32_t)(((wn + (lane & 7)) * PADK + k0 + ((lane >> 3) & 1) * 8) * 2);
            uint32_t bh[8][2], bl[8][2];
#pragma unroll
            for (int ni = 0; ni < 8; ++ni) {
                uint32_t o = b_off + (uint32_t)(ni * 8 * PADK * 2);
                ldsm_x2(bh[ni], uBh + o);
                ldsm_x2(bl[ni], uBl + o);
            }
#pragma unroll
            for (int ni = 0; ni < 8; ++ni) {
                mma16816(acc[ni], ah, bh[ni]);
                mma16816(acc[ni], ah, bl[ni]);
                mma16816(acc[ni], al, bh[ni]);
            }
        }

#pragma unroll
        for (int half = 0; half < 2; ++half) {
            int r = wm + gid + half * 8;
            int m = m0 + r;
            if (m >= M) continue;
#pragma unroll
            for (int ni = 0; ni < 8; ++ni) {
                int col = wn + ni * 8 + tig * 2;
                __half2 hv = __floats2half2_rn(acc[ni][half * 2], acc[ni][half * 2 + 1]);
                *reinterpret_cast<__half2*>(S + (size_t)m * 512 + u * 128 + col) = hv;
            }
        }
    }
}

// ---------------------------------------------------------------------------
// Edge head: warp per edge, fp16 S table
// ---------------------------------------------------------------------------
__global__ __launch_bounds__(256)
void k_edge(const int* __restrict__ ei,
            const __half* __restrict__ S,
            const float* __restrict__ bm1, const float* __restrict__ Wm2,
            const float* __restrict__ bm2,
            const float* __restrict__ bv1, const float* __restrict__ Wv2,
            const float* __restrict__ bv2,
            float* __restrict__ outMean, float* __restrict__ outVar, int E)
{
    int g = blockIdx.x * blockDim.x + threadIdx.x;
    int e = g >> 5, lane = g & 31;
    if (e >= E) return;

    float4 c_bm1 = *reinterpret_cast<const float4*>(&bm1[lane * 4]);
    float4 c_wm2 = *reinterpret_cast<const float4*>(&Wm2[lane * 4]);
    float4 c_bv1 = *reinterpret_cast<const float4*>(&bv1[lane * 4]);
    float4 c_wv2 = *reinterpret_cast<const float4*>(&Wv2[lane * 4]);

    int s = ei[e];
    int d = ei[(size_t)E + e];
    const __half* Sp = S + (size_t)s * 512;
    const __half* Dp = S + (size_t)d * 512;

    __half2 am2[2], cv2[2], bm2h[2], dv2[2];
    *reinterpret_cast<uint2*>(am2)  = *reinterpret_cast<const uint2*>(Sp + lane * 4);
    *reinterpret_cast<uint2*>(cv2)  = *reinterpret_cast<const uint2*>(Sp + 128 + lane * 4);
    *reinterpret_cast<uint2*>(bm2h) = *reinterpret_cast<const uint2*>(Dp + 256 + lane * 4);
    *reinterpret_cast<uint2*>(dv2)  = *reinterpret_cast<const uint2*>(Dp + 384 + lane * 4);

    float2 am0 = __half22float2(am2[0]),  am1 = __half22float2(am2[1]);
    float2 cv0 = __half22float2(cv2[0]),  cv1 = __half22float2(cv2[1]);
    float2 bm0 = __half22float2(bm2h[0]), bm1f = __half22float2(bm2h[1]);
    float2 dv0 = __half22float2(dv2[0]),  dv1 = __half22float2(dv2[1]);

    float pm = fmaxf(am0.x + bm0.x + c_bm1.x, 0.f) * c_wm2.x
             + fmaxf(am0.y + bm0.y + c_bm1.y, 0.f) * c_wm2.y
             + fmaxf(am1.x + bm1f.x + c_bm1.z, 0.f) * c_wm2.z
             + fmaxf(am1.y + bm1f.y + c_bm1.w, 0.f) * c_wm2.w;
    float pv = fmaxf(cv0.x + dv0.x + c_bv1.x, 0.f) * c_wv2.x
             + fmaxf(cv0.y + dv0.y + c_bv1.y, 0.f) * c_wv2.y
             + fmaxf(cv1.x + dv1.x + c_bv1.z, 0.f) * c_wv2.z
             + fmaxf(cv1.y + dv1.y + c_bv1.w, 0.f) * c_wv2.w;

#pragma unroll
    for (int off = 16; off > 0; off >>= 1) {
        pm += __shfl_xor_sync(0xFFFFFFFFu, pm, off);
        pv += __shfl_xor_sync(0xFFFFFFFFu, pv, off);
    }
    if (lane == 0) {
        outMean[e] = pm + bm2[0];
        outVar[e]  = expf(0.5f * (pv + bv2[0]));
    }
}

// ---------------------------------------------------------------------------
// kernel_launch
// ---------------------------------------------------------------------------
extern "C" void kernel_launch(void* const* d_in, const int* in_sizes, int n_in,
                              void* d_out, int out_size)
{
    const float* x       = (const float*)d_in[0];
    const int*   ei      = (const int*)d_in[1];
    const float* W1_rel  = (const float*)d_in[2];
    const float* b1      = (const float*)d_in[3];
    const float* W1_root = (const float*)d_in[4];
    const float* W2_rel  = (const float*)d_in[5];
    const float* b2      = (const float*)d_in[6];
    const float* W2_root = (const float*)d_in[7];
    const float* Wm1     = (const float*)d_in[8];
    const float* bm1     = (const float*)d_in[9];
    const float* Wm2     = (const float*)d_in[10];
    const float* bm2     = (const float*)d_in[11];
    const float* Wv1     = (const float*)d_in[12];
    const float* bv1     = (const float*)d_in[13];
    const float* Wv2     = (const float*)d_in[14];
    const float* bv2     = (const float*)d_in[15];

    int N = in_sizes[0] / DH;     // 50000
    int E = in_sizes[1] / 2;      // 800000
    float* out   = (float*)d_out;
    int    Ehalf = out_size / 2;

    float *agg, *h1;
    __half* S;
    __nv_bfloat16 *h1h, *h1l, *h2h, *h2l, *Wh, *Wl;
    int *deg, *off, *cursor, *csr;
    cudaGetSymbolAddress((void**)&agg,    g_agg);
    cudaGetSymbolAddress((void**)&h1,     g_h1);
    cudaGetSymbolAddress((void**)&S,      g_S);
    cudaGetSymbolAddress((void**)&h1h,    g_h1h);
    cudaGetSymbolAddress((void**)&h1l,    g_h1l);
    cudaGetSymbolAddress((void**)&h2h,    g_h2h);
    cudaGetSymbolAddress((void**)&h2l,    g_h2l);
    cudaGetSymbolAddress((void**)&Wh,     g_Wh);
    cudaGetSymbolAddress((void**)&Wl,     g_Wl);
    cudaGetSymbolAddress((void**)&deg,    g_deg);
    cudaGetSymbolAddress((void**)&off,    g_off);
    cudaGetSymbolAddress((void**)&cursor, g_cursor);
    cudaGetSymbolAddress((void**)&csr,    g_csr);

    const int DYN_SMEM = 4 * 128 * PADK * 2;   // 139264 B
    static int smem_set = 0;
    if (!smem_set) {
        cudaFuncSetAttribute(k_gemm_mma,  cudaFuncAttributeMaxDynamicSharedMemorySize, DYN_SMEM);
        cudaFuncSetAttribute(k_gemm_head, cudaFuncAttributeMaxDynamicSharedMemorySize, DYN_SMEM);
        smem_set = 1;
    }

    int gemmB   = (N + MTILE - 1) / MTILE;
    int edgeB   = (E * 32 + 255) / 256;
    int gatherB = (N * 32 + 255) / 256;
    int eB      = (E + 255) / 256;

    // Weight prep
    WSrc ws;
    ws.p[0] = W1_rel;  ws.p[1] = W1_root;
    ws.p[2] = W2_rel;  ws.p[3] = W2_root;
    ws.p[4] = Wm1;     ws.p[5] = Wv1;
    ws.p[6] = Wm1 + 128 * DH;  ws.p[7] = Wv1 + 128 * DH;
    k_wprep<<<dim3(64, 8), 256>>>(ws, Wh, Wl);

    // CSR build (per launch; reused by both layers)
    k_zeroi<<<(N + 256) / 256, 256>>>(deg, N + 1);
    k_hist<<<eB, 256>>>(ei, E, deg);
    k_scan<<<1, 1024>>>(deg, off, cursor, N);
    k_fill<<<eB, 256>>>(ei, E, cursor, csr);

    // Layer 1
    k_gather<<<gatherB, 256>>>(x, csr, off, agg, N);
    k_gemm_mma<<<gemmB, 512, DYN_SMEM>>>(
        agg, nullptr, nullptr, Wh + 0 * 16384, Wl + 0 * 16384,
        x,   nullptr, nullptr, Wh + 1 * 16384, Wl + 1 * 16384,
        b1, h1, h1h, h1l, N, 1);

    // Layer 2
    k_gather<<<gatherB, 256>>>(h1, csr, off, agg, N);
    k_gemm_mma<<<gemmB, 512, DYN_SMEM>>>(
        agg,     nullptr, nullptr, Wh + 2 * 16384, Wl + 2 * 16384,
        nullptr, h1h,     h1l,     Wh + 3 * 16384, Wl + 3 * 16384,
        b2, nullptr, h2h, h2l, N, 1);

    // Head node tables
    k_gemm_head<<<gemmB, 512, DYN_SMEM>>>(h2h, h2l,
                                          Wh + 4 * 16384, Wl + 4 * 16384, S, N);

    // Edge heads
    k_edge<<<edgeB, 256>>>(ei, S, bm1, Wm2, bm2, bv1, Wv2, bv2,
                           out, out + Ehalf, E);
}

// round 13
// speedup vs baseline: 1.9146x; 1.0905x over previous
#include <cuda_runtime.h>
#include <cuda_bf16.h>
#include <cuda_fp16.h>
#include <math.h>
#include <stdint.h>

#define NMAX 50000
#define EMAX 800000
#define DH   128
#define MTILE 128
#define PADK 136      // bf16 elements per padded SMEM row (272 B)

// ---------------------------------------------------------------------------
// Scratch (__device__ globals; allocation-free rule)
// ---------------------------------------------------------------------------
__device__ float g_agg[(size_t)NMAX * DH];
__device__ float g_h1 [(size_t)NMAX * DH];
__device__ __half g_S [(size_t)NMAX * 512];   // fp16 [Am|Cv|Bm|Dv] per node

__device__ __nv_bfloat16 g_h1h [(size_t)NMAX * DH];
__device__ __nv_bfloat16 g_h1l [(size_t)NMAX * DH];
__device__ __nv_bfloat16 g_h2h [(size_t)NMAX * DH];
__device__ __nv_bfloat16 g_h2l [(size_t)NMAX * DH];
__device__ __nv_bfloat16 g_Wh[8 * 128 * 128];
__device__ __nv_bfloat16 g_Wl[8 * 128 * 128];

// CSR scratch
__device__ int g_deg   [NMAX + 64];
__device__ int g_off   [NMAX + 64];
__device__ int g_cursor[NMAX + 64];
__device__ int g_csr   [EMAX];

// ---------------------------------------------------------------------------
// helpers
// ---------------------------------------------------------------------------
__device__ __forceinline__ uint32_t smem_to_u32(const void* p) {
    uint32_t a;
    asm("{ .reg .u64 t; cvta.to.shared.u64 t, %1; cvt.u32.u64 %0, t; }"
        : "=r"(a) : "l"(p));
    return a;
}
__device__ __forceinline__ void ldsm_x4(uint32_t* r, uint32_t addr) {
    asm volatile("ldmatrix.sync.aligned.m8n8.x4.shared.b16 {%0,%1,%2,%3}, [%4];"
                 : "=r"(r[0]), "=r"(r[1]), "=r"(r[2]), "=r"(r[3]) : "r"(addr));
}
__device__ __forceinline__ void ldsm_x2(uint32_t* r, uint32_t addr) {
    asm volatile("ldmatrix.sync.aligned.m8n8.x2.shared.b16 {%0,%1}, [%2];"
                 : "=r"(r[0]), "=r"(r[1]) : "r"(addr));
}
__device__ __forceinline__ void mma16816(float* c, const uint32_t* a, const uint32_t* b) {
    asm volatile(
        "mma.sync.aligned.m16n8k16.row.col.f32.bf16.bf16.f32 "
        "{%0,%1,%2,%3}, {%4,%5,%6,%7}, {%8,%9}, {%0,%1,%2,%3};"
        : "+f"(c[0]), "+f"(c[1]), "+f"(c[2]), "+f"(c[3])
        : "r"(a[0]), "r"(a[1]), "r"(a[2]), "r"(a[3]), "r"(b[0]), "r"(b[1]));
}
__device__ __forceinline__ void split2(float v0, float v1, uint32_t& hi, uint32_t& lo)
{
    __nv_bfloat162 h;
    h.x = __float2bfloat16(v0);
    h.y = __float2bfloat16(v1);
    __nv_bfloat162 l;
    l.x = __float2bfloat16(v0 - __bfloat162float(h.x));
    l.y = __float2bfloat16(v1 - __bfloat162float(h.y));
    hi = *reinterpret_cast<uint32_t*>(&h);
    lo = *reinterpret_cast<uint32_t*>(&l);
}

// ---------------------------------------------------------------------------
// CSR build
// ---------------------------------------------------------------------------
__global__ void k_zeroi(int* __restrict__ p, int n)
{
    int i = blockIdx.x * blockDim.x + threadIdx.x;
    if (i < n) p[i] = 0;
}

__global__ void k_hist(const int* __restrict__ ei, int E, int* __restrict__ deg)
{
    int e = blockIdx.x * blockDim.x + threadIdx.x;
    if (e < E) atomicAdd(&deg[ei[(size_t)E + e]], 1);
}

// single-block tile-sequential scan: coalesced loads, warp-shuffle scan,
// cross-warp smem scan, running carry. 1024 threads.
__global__ void k_scan(const int* __restrict__ deg, int* __restrict__ off,
                       int* __restrict__ cursor, int N)
{
    __shared__ int sWarp[32];
    __shared__ int sCarry;
    const int t    = threadIdx.x;
    const int lane = t & 31;
    const int w    = t >> 5;
    if (t == 0) sCarry = 0;
    __syncthreads();

    const int nTiles = (N + 1023) >> 10;
    for (int tile = 0; tile < nTiles; ++tile) {
        int i = (tile << 10) + t;
        int v = (i < N) ? deg[i] : 0;

        // warp inclusive scan
        int x = v;
#pragma unroll
        for (int d = 1; d < 32; d <<= 1) {
            int y = __shfl_up_sync(0xFFFFFFFFu, x, d);
            if (lane >= d) x += y;
        }
        if (lane == 31) sWarp[w] = x;
        __syncthreads();
        if (w == 0) {
            int s = sWarp[lane];
#pragma unroll
            for (int d = 1; d < 32; d <<= 1) {
                int y = __shfl_up_sync(0xFFFFFFFFu, s, d);
                if (lane >= d) s += y;
            }
            sWarp[lane] = s;
        }
        __syncthreads();

        int warpBase = (w > 0) ? sWarp[w - 1] : 0;
        int excl = sCarry + warpBase + (x - v);
        if (i < N) { off[i] = excl; cursor[i] = excl; }
        int total = sWarp[31];
        __syncthreads();            // everyone has read sCarry/sWarp
        if (t == 0) sCarry += total;
        __syncthreads();
    }
    if (t == 0) off[N] = sCarry;
}

__global__ void k_fill(const int* __restrict__ ei, int E,
                       int* __restrict__ cursor, int* __restrict__ csr)
{
    int e = blockIdx.x * blockDim.x + threadIdx.x;
    if (e >= E) return;
    int s = ei[e];
    int d = ei[(size_t)E + e];
    int pos = atomicAdd(&cursor[d], 1);
    csr[pos] = s;
}

// ---------------------------------------------------------------------------
// gather-reduce: agg[n] = sum over edges (dst=n) of feat[src]; warp per node
// ---------------------------------------------------------------------------
__global__ void k_gather(const float* __restrict__ feat,
                         const int* __restrict__ csr, const int* __restrict__ off,
                         float* __restrict__ agg, int N)
{
    int g = blockIdx.x * blockDim.x + threadIdx.x;
    int n = g >> 5, lane = g & 31;
    if (n >= N) return;
    int s0 = off[n], s1 = off[n + 1];
    float4 acc = make_float4(0.f, 0.f, 0.f, 0.f);
    for (int base = s0; base < s1; base += 32) {
        int cnt = min(32, s1 - base);
        int idx = (base + lane < s1) ? csr[base + lane] : 0;
#pragma unroll 4
        for (int j = 0; j < cnt; ++j) {
            int s = __shfl_sync(0xFFFFFFFFu, idx, j);
            float4 v = *reinterpret_cast<const float4*>(&feat[(size_t)s * DH + lane * 4]);
            acc.x += v.x; acc.y += v.y; acc.z += v.z; acc.w += v.w;
        }
    }
    *reinterpret_cast<float4*>(&agg[(size_t)n * DH + lane * 4]) = acc;
}

// ---------------------------------------------------------------------------
// weight prep: transpose [k][n] -> [n][k], split to bf16 hi/lo. 8 units.
// ---------------------------------------------------------------------------
struct WSrc { const float* p[8]; };

__global__ void k_wprep(WSrc w,
                        __nv_bfloat16* __restrict__ oh,
                        __nv_bfloat16* __restrict__ ol)
{
    int u = blockIdx.y;
    int i = blockIdx.x * 256 + threadIdx.x;
    int n = i >> 7, k = i & 127;
    float v = w.p[u][(size_t)k * DH + n];
    __nv_bfloat16 h = __float2bfloat16(v);
    oh[(size_t)u * 16384 + i] = h;
    ol[(size_t)u * 16384 + i] = __float2bfloat16(v - __bfloat162float(h));
}

// ---------------------------------------------------------------------------
// mma.sync bf16 GEMM, error-compensated split (hi*hi + hi*lo + lo*hi).
// 512 threads, 16 warps, warp tile 16x64 (8 m-groups x 2 n-groups).
// ---------------------------------------------------------------------------
__global__ __launch_bounds__(512)
void k_gemm_mma(const float* __restrict__ a0f,
                const __nv_bfloat16* __restrict__ a0h, const __nv_bfloat16* __restrict__ a0l,
                const __nv_bfloat16* __restrict__ w0h, const __nv_bfloat16* __restrict__ w0l,
                const float* __restrict__ a1f,
                const __nv_bfloat16* __restrict__ a1h, const __nv_bfloat16* __restrict__ a1l,
                const __nv_bfloat16* __restrict__ w1h, const __nv_bfloat16* __restrict__ w1l,
                const float* __restrict__ bias,
                float* __restrict__ cf,
                __nv_bfloat16* __restrict__ chi, __nv_bfloat16* __restrict__ clo,
                int M, int relu)
{
    extern __shared__ __nv_bfloat16 sm[];
    __nv_bfloat16* sAh = sm;
    __nv_bfloat16* sAl = sAh + 128 * PADK;
    __nv_bfloat16* sBh = sAl + 128 * PADK;
    __nv_bfloat16* sBl = sBh + 128 * PADK;

    const int tid  = threadIdx.x;
    const int wid  = tid >> 5;
    const int lane = tid & 31;
    const int m0   = blockIdx.x * MTILE;
    const int wm   = (wid >> 1) * 16;
    const int wn   = (wid & 1) * 64;

    const uint32_t uAh = smem_to_u32(sAh);
    const uint32_t uAl = smem_to_u32(sAl);
    const uint32_t uBh = smem_to_u32(sBh);
    const uint32_t uBl = smem_to_u32(sBl);

    float acc[8][4];
#pragma unroll
    for (int ni = 0; ni < 8; ++ni)
#pragma unroll
        for (int q = 0; q < 4; ++q) acc[ni][q] = 0.f;

#pragma unroll 1
    for (int phase = 0; phase < 2; ++phase) {
        const float*         Af = phase ? a1f : a0f;
        const __nv_bfloat16* Ah = phase ? a1h : a0h;
        const __nv_bfloat16* Al = phase ? a1l : a0l;
        const __nv_bfloat16* Wh = phase ? w1h : w0h;
        const __nv_bfloat16* Wl = phase ? w1l : w0l;
        if (Af == nullptr && Ah == nullptr) break;

        __syncthreads();
#pragma unroll
        for (int it = 0; it < 4; ++it) {
            int idx = tid + it * 512;          // 0..2047 uint4 slots
            int row = idx >> 4;
            int c8  = (idx & 15) << 3;
            size_t soff = (size_t)row * PADK + c8;
            uint4 vh = make_uint4(0, 0, 0, 0), vl = vh;
            if (m0 + row < M) {
                if (Af) {
                    const float* ap = Af + (size_t)(m0 + row) * DH + c8;
                    float4 f0 = *reinterpret_cast<const float4*>(ap);
                    float4 f1 = *reinterpret_cast<const float4*>(ap + 4);
                    split2(f0.x, f0.y, vh.x, vl.x);
                    split2(f0.z, f0.w, vh.y, vl.y);
                    split2(f1.x, f1.y, vh.z, vl.z);
                    split2(f1.z, f1.w, vh.w, vl.w);
                } else {
                    vh = *reinterpret_cast<const uint4*>(Ah + (size_t)(m0 + row) * DH + c8);
                    vl = *reinterpret_cast<const uint4*>(Al + (size_t)(m0 + row) * DH + c8);
                }
            }
            *reinterpret_cast<uint4*>(sAh + soff) = vh;
            *reinterpret_cast<uint4*>(sAl + soff) = vl;
            *reinterpret_cast<uint4*>(sBh + soff) =
                *reinterpret_cast<const uint4*>(Wh + (size_t)row * DH + c8);
            *reinterpret_cast<uint4*>(sBl + soff) =
                *reinterpret_cast<const uint4*>(Wl + (size_t)row * DH + c8);
        }
        __syncthreads();

#pragma unroll 1
        for (int kc = 0; kc < 8; ++kc) {
            int k0 = kc * 16;
            uint32_t a_off = (uint32_t)(((wm + (lane & 15)) * PADK + k0 + (lane >> 4) * 8) * 2);
            uint32_t ah[4], al[4];
            ldsm_x4(ah, uAh + a_off);
            ldsm_x4(al, uAl + a_off);
            uint32_t b_off = (uint32_t)(((wn + (lane & 7)) * PADK + k0 + ((lane >> 3) & 1) * 8) * 2);
            uint32_t bh[8][2], bl[8][2];
#pragma unroll
            for (int ni = 0; ni < 8; ++ni) {
                uint32_t o = b_off + (uint32_t)(ni * 8 * PADK * 2);
                ldsm_x2(bh[ni], uBh + o);
                ldsm_x2(bl[ni], uBl + o);
            }
#pragma unroll
            for (int ni = 0; ni < 8; ++ni) {
                mma16816(acc[ni], ah, bh[ni]);
                mma16816(acc[ni], ah, bl[ni]);
                mma16816(acc[ni], al, bh[ni]);
            }
        }
    }

    const int gid = lane >> 2, tig = lane & 3;
#pragma unroll
    for (int half = 0; half < 2; ++half) {
        int r = wm + gid + half * 8;
        int m = m0 + r;
        if (m >= M) continue;
#pragma unroll
        for (int ni = 0; ni < 8; ++ni) {
            int col = wn + ni * 8 + tig * 2;
            float v0 = acc[ni][half * 2];
            float v1 = acc[ni][half * 2 + 1];
            if (bias) { v0 += bias[col]; v1 += bias[col + 1]; }
            if (relu) { v0 = fmaxf(v0, 0.f); v1 = fmaxf(v1, 0.f); }
            if (cf)
                *reinterpret_cast<float2*>(cf + (size_t)m * DH + col) = make_float2(v0, v1);
            if (chi) {
                uint32_t ph, pl;
                split2(v0, v1, ph, pl);
                *reinterpret_cast<uint32_t*>(chi + (size_t)m * DH + col) = ph;
                *reinterpret_cast<uint32_t*>(clo + (size_t)m * DH + col) = pl;
            }
        }
    }
}

// ---------------------------------------------------------------------------
// Merged head GEMM: A (h2 hi/lo) loaded once; 4 weight units; fp16 S out.
// 512 threads, 16 warps, warp tile 16x64.
// ---------------------------------------------------------------------------
__global__ __launch_bounds__(512)
void k_gemm_head(const __nv_bfloat16* __restrict__ ah_, const __nv_bfloat16* __restrict__ al_,
                 const __nv_bfloat16* __restrict__ Wh4, const __nv_bfloat16* __restrict__ Wl4,
                 __half* __restrict__ S, int M)
{
    extern __shared__ __nv_bfloat16 sm[];
    __nv_bfloat16* sAh = sm;
    __nv_bfloat16* sAl = sAh + 128 * PADK;
    __nv_bfloat16* sBh = sAl + 128 * PADK;
    __nv_bfloat16* sBl = sBh + 128 * PADK;

    const int tid  = threadIdx.x;
    const int wid  = tid >> 5;
    const int lane = tid & 31;
    const int m0   = blockIdx.x * MTILE;
    const int wm   = (wid >> 1) * 16;
    const int wn   = (wid & 1) * 64;

    const uint32_t uAh = smem_to_u32(sAh);
    const uint32_t uAl = smem_to_u32(sAl);
    const uint32_t uBh = smem_to_u32(sBh);
    const uint32_t uBl = smem_to_u32(sBl);

#pragma unroll
    for (int it = 0; it < 4; ++it) {
        int idx = tid + it * 512;
        int row = idx >> 4;
        int c8  = (idx & 15) << 3;
        size_t soff = (size_t)row * PADK + c8;
        uint4 vh = make_uint4(0, 0, 0, 0), vl = vh;
        if (m0 + row < M) {
            vh = *reinterpret_cast<const uint4*>(ah_ + (size_t)(m0 + row) * DH + c8);
            vl = *reinterpret_cast<const uint4*>(al_ + (size_t)(m0 + row) * DH + c8);
        }
        *reinterpret_cast<uint4*>(sAh + soff) = vh;
        *reinterpret_cast<uint4*>(sAl + soff) = vl;
    }

    const int gid = lane >> 2, tig = lane & 3;

#pragma unroll 1
    for (int u = 0; u < 4; ++u) {
        const __nv_bfloat16* Wh = Wh4 + (size_t)u * 16384;
        const __nv_bfloat16* Wl = Wl4 + (size_t)u * 16384;

        __syncthreads();
#pragma unroll
        for (int it = 0; it < 4; ++it) {
            int idx = tid + it * 512;
            int row = idx >> 4;
            int c8  = (idx & 15) << 3;
            size_t soff = (size_t)row * PADK + c8;
            *reinterpret_cast<uint4*>(sBh + soff) =
                *reinterpret_cast<const uint4*>(Wh + (size_t)row * DH + c8);
            *reinterpret_cast<uint4*>(sBl + soff) =
                *reinterpret_cast<const uint4*>(Wl + (size_t)row * DH + c8);
        }
        __syncthreads();

        float acc[8][4];
#pragma unroll
        for (int ni = 0; ni < 8; ++ni)
#pragma unroll
            for (int q = 0; q < 4; ++q) acc[ni][q] = 0.f;

#pragma unroll 1
        for (int kc = 0; kc < 8; ++kc) {
            int k0 = kc * 16;
            uint32_t a_off = (uint32_t)(((wm + (lane & 15)) * PADK + k0 + (lane >> 4) * 8) * 2);
            uint32_t ah[4], al[4];
            ldsm_x4(ah, uAh + a_off);
            ldsm_x4(al, uAl + a_off);
            uint32_t b_off = (uint32_t)(((wn + (lane & 7)) * PADK + k0 + ((lane >> 3) & 1) * 8) * 2);
            uint32_t bh[8][2], bl[8][2];
#pragma unroll
            for (int ni = 0; ni < 8; ++ni) {
                uint32_t o = b_off + (uint32_t)(ni * 8 * PADK * 2);
                ldsm_x2(bh[ni], uBh + o);
                ldsm_x2(bl[ni], uBl + o);
            }
#pragma unroll
            for (int ni = 0; ni < 8; ++ni) {
                mma16816(acc[ni], ah, bh[ni]);
                mma16816(acc[ni], ah, bl[ni]);
                mma16816(acc[ni], al, bh[ni]);
            }
        }

#pragma unroll
        for (int half = 0; half < 2; ++half) {
            int r = wm + gid + half * 8;
            int m = m0 + r;
            if (m >= M) continue;
#pragma unroll
            for (int ni = 0; ni < 8; ++ni) {
                int col = wn + ni * 8 + tig * 2;
                __half2 hv = __floats2half2_rn(acc[ni][half * 2], acc[ni][half * 2 + 1]);
                *reinterpret_cast<__half2*>(S + (size_t)m * 512 + u * 128 + col) = hv;
            }
        }
    }
}

// ---------------------------------------------------------------------------
// Edge head: warp per edge, fp16 S table
// ---------------------------------------------------------------------------
__global__ __launch_bounds__(256)
void k_edge(const int* __restrict__ ei,
            const __half* __restrict__ S,
            const float* __restrict__ bm1, const float* __restrict__ Wm2,
            const float* __restrict__ bm2,
            const float* __restrict__ bv1, const float* __restrict__ Wv2,
            const float* __restrict__ bv2,
            float* __restrict__ outMean, float* __restrict__ outVar, int E)
{
    int g = blockIdx.x * blockDim.x + threadIdx.x;
    int e = g >> 5, lane = g & 31;
    if (e >= E) return;

    float4 c_bm1 = *reinterpret_cast<const float4*>(&bm1[lane * 4]);
    float4 c_wm2 = *reinterpret_cast<const float4*>(&Wm2[lane * 4]);
    float4 c_bv1 = *reinterpret_cast<const float4*>(&bv1[lane * 4]);
    float4 c_wv2 = *reinterpret_cast<const float4*>(&Wv2[lane * 4]);

    int s = ei[e];
    int d = ei[(size_t)E + e];
    const __half* Sp = S + (size_t)s * 512;
    const __half* Dp = S + (size_t)d * 512;

    __half2 am2[2], cv2[2], bm2h[2], dv2[2];
    *reinterpret_cast<uint2*>(am2)  = *reinterpret_cast<const uint2*>(Sp + lane * 4);
    *reinterpret_cast<uint2*>(cv2)  = *reinterpret_cast<const uint2*>(Sp + 128 + lane * 4);
    *reinterpret_cast<uint2*>(bm2h) = *reinterpret_cast<const uint2*>(Dp + 256 + lane * 4);
    *reinterpret_cast<uint2*>(dv2)  = *reinterpret_cast<const uint2*>(Dp + 384 + lane * 4);

    float2 am0 = __half22float2(am2[0]),  am1 = __half22float2(am2[1]);
    float2 cv0 = __half22float2(cv2[0]),  cv1 = __half22float2(cv2[1]);
    float2 bm0 = __half22float2(bm2h[0]), bm1f = __half22float2(bm2h[1]);
    float2 dv0 = __half22float2(dv2[0]),  dv1 = __half22float2(dv2[1]);

    float pm = fmaxf(am0.x + bm0.x + c_bm1.x, 0.f) * c_wm2.x
             + fmaxf(am0.y + bm0.y + c_bm1.y, 0.f) * c_wm2.y
             + fmaxf(am1.x + bm1f.x + c_bm1.z, 0.f) * c_wm2.z
             + fmaxf(am1.y + bm1f.y + c_bm1.w, 0.f) * c_wm2.w;
    float pv = fmaxf(cv0.x + dv0.x + c_bv1.x, 0.f) * c_wv2.x
             + fmaxf(cv0.y + dv0.y + c_bv1.y, 0.f) * c_wv2.y
             + fmaxf(cv1.x + dv1.x + c_bv1.z, 0.f) * c_wv2.z
             + fmaxf(cv1.y + dv1.y + c_bv1.w, 0.f) * c_wv2.w;

#pragma unroll
    for (int off = 16; off > 0; off >>= 1) {
        pm += __shfl_xor_sync(0xFFFFFFFFu, pm, off);
        pv += __shfl_xor_sync(0xFFFFFFFFu, pv, off);
    }
    if (lane == 0) {
        outMean[e] = pm + bm2[0];
        outVar[e]  = expf(0.5f * (pv + bv2[0]));
    }
}

// ---------------------------------------------------------------------------
// kernel_launch
// ---------------------------------------------------------------------------
extern "C" void kernel_launch(void* const* d_in, const int* in_sizes, int n_in,
                              void* d_out, int out_size)
{
    const float* x       = (const float*)d_in[0];
    const int*   ei      = (const int*)d_in[1];
    const float* W1_rel  = (const float*)d_in[2];
    const float* b1      = (const float*)d_in[3];
    const float* W1_root = (const float*)d_in[4];
    const float* W2_rel  = (const float*)d_in[5];
    const float* b2      = (const float*)d_in[6];
    const float* W2_root = (const float*)d_in[7];
    const float* Wm1     = (const float*)d_in[8];
    const float* bm1     = (const float*)d_in[9];
    const float* Wm2     = (const float*)d_in[10];
    const float* bm2     = (const float*)d_in[11];
    const float* Wv1     = (const float*)d_in[12];
    const float* bv1     = (const float*)d_in[13];
    const float* Wv2     = (const float*)d_in[14];
    const float* bv2     = (const float*)d_in[15];

    int N = in_sizes[0] / DH;     // 50000
    int E = in_sizes[1] / 2;      // 800000
    float* out   = (float*)d_out;
    int    Ehalf = out_size / 2;

    float *agg, *h1;
    __half* S;
    __nv_bfloat16 *h1h, *h1l, *h2h, *h2l, *Wh, *Wl;
    int *deg, *off, *cursor, *csr;
    cudaGetSymbolAddress((void**)&agg,    g_agg);
    cudaGetSymbolAddress((void**)&h1,     g_h1);
    cudaGetSymbolAddress((void**)&S,      g_S);
    cudaGetSymbolAddress((void**)&h1h,    g_h1h);
    cudaGetSymbolAddress((void**)&h1l,    g_h1l);
    cudaGetSymbolAddress((void**)&h2h,    g_h2h);
    cudaGetSymbolAddress((void**)&h2l,    g_h2l);
    cudaGetSymbolAddress((void**)&Wh,     g_Wh);
    cudaGetSymbolAddress((void**)&Wl,     g_Wl);
    cudaGetSymbolAddress((void**)&deg,    g_deg);
    cudaGetSymbolAddress((void**)&off,    g_off);
    cudaGetSymbolAddress((void**)&cursor, g_cursor);
    cudaGetSymbolAddress((void**)&csr,    g_csr);

    const int DYN_SMEM = 4 * 128 * PADK * 2;   // 139264 B
    static int smem_set = 0;
    if (!smem_set) {
        cudaFuncSetAttribute(k_gemm_mma,  cudaFuncAttributeMaxDynamicSharedMemorySize, DYN_SMEM);
        cudaFuncSetAttribute(k_gemm_head, cudaFuncAttributeMaxDynamicSharedMemorySize, DYN_SMEM);
        smem_set = 1;
    }

    int gemmB   = (N + MTILE - 1) / MTILE;
    int edgeB   = (E * 32 + 255) / 256;
    int gatherB = (N * 32 + 255) / 256;
    int eB      = (E + 255) / 256;

    // Weight prep
    WSrc ws;
    ws.p[0] = W1_rel;  ws.p[1] = W1_root;
    ws.p[2] = W2_rel;  ws.p[3] = W2_root;
    ws.p[4] = Wm1;     ws.p[5] = Wv1;
    ws.p[6] = Wm1 + 128 * DH;  ws.p[7] = Wv1 + 128 * DH;
    k_wprep<<<dim3(64, 8), 256>>>(ws, Wh, Wl);

    // CSR build (per launch; reused by both layers)
    k_zeroi<<<(N + 256) / 256, 256>>>(deg, N + 1);
    k_hist<<<eB, 256>>>(ei, E, deg);
    k_scan<<<1, 1024>>>(deg, off, cursor, N);
    k_fill<<<eB, 256>>>(ei, E, cursor, csr);

    // Layer 1
    k_gather<<<gatherB, 256>>>(x, csr, off, agg, N);
    k_gemm_mma<<<gemmB, 512, DYN_SMEM>>>(
        agg, nullptr, nullptr, Wh + 0 * 16384, Wl + 0 * 16384,
        x,   nullptr, nullptr, Wh + 1 * 16384, Wl + 1 * 16384,
        b1, h1, h1h, h1l, N, 1);

    // Layer 2
    k_gather<<<gatherB, 256>>>(h1, csr, off, agg, N);
    k_gemm_mma<<<gemmB, 512, DYN_SMEM>>>(
        agg,     nullptr, nullptr, Wh + 2 * 16384, Wl + 2 * 16384,
        nullptr, h1h,     h1l,     Wh + 3 * 16384, Wl + 3 * 16384,
        b2, nullptr, h2h, h2l, N, 1);

    // Head node tables
    k_gemm_head<<<gemmB, 512, DYN_SMEM>>>(h2h, h2l,
                                          Wh + 4 * 16384, Wl + 4 * 16384, S, N);

    // Edge heads
    k_edge<<<edgeB, 256>>>(ei, S, bm1, Wm2, bm2, bv1, Wv2, bv2,
                           out, out + Ehalf, E);
}

// round 14
// speedup vs baseline: 2.0550x; 1.0733x over previous
#include <cuda_runtime.h>
#include <cuda_bf16.h>
#include <cuda_fp16.h>
#include <math.h>
#include <stdint.h>

#define NMAX 50000
#define EMAX 800000
#define DH   128
#define MTILE 128
#define PADK 136      // bf16 elements per padded SMEM row (272 B)

// ---------------------------------------------------------------------------
// Scratch (__device__ globals; allocation-free rule)
// ---------------------------------------------------------------------------
__device__ float g_agg[(size_t)NMAX * DH];
__device__ float g_h1 [(size_t)NMAX * DH];
__device__ __half g_S [(size_t)NMAX * 512];   // fp16 [Am|Cv|Bm|Dv] per node

__device__ __nv_bfloat16 g_h1h [(size_t)NMAX * DH];
__device__ __nv_bfloat16 g_h1l [(size_t)NMAX * DH];
__device__ __nv_bfloat16 g_h2h [(size_t)NMAX * DH];
__device__ __nv_bfloat16 g_h2l [(size_t)NMAX * DH];
__device__ __nv_bfloat16 g_Wh[8 * 128 * 128];
__device__ __nv_bfloat16 g_Wl[8 * 128 * 128];

// CSR scratch
__device__ int g_deg   [NMAX + 64];
__device__ int g_off   [NMAX + 64];
__device__ int g_cursor[NMAX + 64];
__device__ int g_csr   [EMAX];
__device__ int g_blk   [128];      // per-block sums for the scan

// ---------------------------------------------------------------------------
// helpers
// ---------------------------------------------------------------------------
__device__ __forceinline__ uint32_t smem_to_u32(const void* p) {
    uint32_t a;
    asm("{ .reg .u64 t; cvta.to.shared.u64 t, %1; cvt.u32.u64 %0, t; }"
        : "=r"(a) : "l"(p));
    return a;
}
__device__ __forceinline__ void ldsm_x4(uint32_t* r, uint32_t addr) {
    asm volatile("ldmatrix.sync.aligned.m8n8.x4.shared.b16 {%0,%1,%2,%3}, [%4];"
                 : "=r"(r[0]), "=r"(r[1]), "=r"(r[2]), "=r"(r[3]) : "r"(addr));
}
__device__ __forceinline__ void ldsm_x2(uint32_t* r, uint32_t addr) {
    asm volatile("ldmatrix.sync.aligned.m8n8.x2.shared.b16 {%0,%1}, [%2];"
                 : "=r"(r[0]), "=r"(r[1]) : "r"(addr));
}
__device__ __forceinline__ void mma16816(float* c, const uint32_t* a, const uint32_t* b) {
    asm volatile(
        "mma.sync.aligned.m16n8k16.row.col.f32.bf16.bf16.f32 "
        "{%0,%1,%2,%3}, {%4,%5,%6,%7}, {%8,%9}, {%0,%1,%2,%3};"
        : "+f"(c[0]), "+f"(c[1]), "+f"(c[2]), "+f"(c[3])
        : "r"(a[0]), "r"(a[1]), "r"(a[2]), "r"(a[3]), "r"(b[0]), "r"(b[1]));
}
__device__ __forceinline__ void split2(float v0, float v1, uint32_t& hi, uint32_t& lo)
{
    __nv_bfloat162 h;
    h.x = __float2bfloat16(v0);
    h.y = __float2bfloat16(v1);
    __nv_bfloat162 l;
    l.x = __float2bfloat16(v0 - __bfloat162float(h.x));
    l.y = __float2bfloat16(v1 - __bfloat162float(h.y));
    hi = *reinterpret_cast<uint32_t*>(&h);
    lo = *reinterpret_cast<uint32_t*>(&l);
}

// ---------------------------------------------------------------------------
// CSR build
// ---------------------------------------------------------------------------
__global__ void k_zeroi(int* __restrict__ p, int n)
{
    int i = blockIdx.x * blockDim.x + threadIdx.x;
    if (i < n) p[i] = 0;
}

__global__ void k_hist(const int* __restrict__ ei, int E, int* __restrict__ deg)
{
    int e = blockIdx.x * blockDim.x + threadIdx.x;
    if (e < E) atomicAdd(&deg[ei[(size_t)E + e]], 1);
}

// Phase 1: per-block scan (1024 elems/block), local exclusive prefix -> off,
// block total -> blk[b]. All blocks concurrent.
__global__ void k_scan1(const int* __restrict__ deg, int* __restrict__ off,
                        int* __restrict__ blk, int N)
{
    __shared__ int sWarp[32];
    const int t    = threadIdx.x;
    const int lane = t & 31;
    const int w    = t >> 5;
    int i = blockIdx.x * 1024 + t;
    int v = (i < N) ? deg[i] : 0;

    int x = v;
#pragma unroll
    for (int d = 1; d < 32; d <<= 1) {
        int y = __shfl_up_sync(0xFFFFFFFFu, x, d);
        if (lane >= d) x += y;
    }
    if (lane == 31) sWarp[w] = x;
    __syncthreads();
    if (w == 0) {
        int s = sWarp[lane];
#pragma unroll
        for (int d = 1; d < 32; d <<= 1) {
            int y = __shfl_up_sync(0xFFFFFFFFu, s, d);
            if (lane >= d) s += y;
        }
        sWarp[lane] = s;
    }
    __syncthreads();
    int warpBase = (w > 0) ? sWarp[w - 1] : 0;
    if (i < N) off[i] = warpBase + (x - v);
    if (t == 1023) blk[blockIdx.x] = sWarp[31];
}

// Phase 2: scan block sums (nB <= 64), write total to off[N]
__global__ void k_scan2(int* __restrict__ blk, int* __restrict__ off, int nB, int N)
{
    const int t = threadIdx.x;   // 64 threads
    int v = (t < nB) ? blk[t] : 0;
    int x = v;
#pragma unroll
    for (int d = 1; d < 32; d <<= 1) {
        int y = __shfl_up_sync(0xFFFFFFFFu, x, d);
        if ((t & 31) >= d) x += y;
    }
    __shared__ int sw[2];
    if ((t & 31) == 31) sw[t >> 5] = x;
    __syncthreads();
    int base = (t >= 32) ? sw[0] : 0;
    int excl = base + x - v;
    if (t < nB) blk[t] = excl;
    if (t == 63) off[N] = base + ((nB > 32) ? sw[1] : ((nB > 0) ? sw[0] : 0));
}

// Phase 3: add block base; write cursor
__global__ void k_scan3(int* __restrict__ off, int* __restrict__ cursor,
                        const int* __restrict__ blk, int N)
{
    int i = blockIdx.x * 1024 + threadIdx.x;
    if (i < N) {
        int o = off[i] + blk[blockIdx.x];
        off[i] = o;
        cursor[i] = o;
    }
}

__global__ void k_fill(const int* __restrict__ ei, int E,
                       int* __restrict__ cursor, int* __restrict__ csr)
{
    int e = blockIdx.x * blockDim.x + threadIdx.x;
    if (e >= E) return;
    int s = ei[e];
    int d = ei[(size_t)E + e];
    int pos = atomicAdd(&cursor[d], 1);
    csr[pos] = s;
}

// ---------------------------------------------------------------------------
// gather-reduce: agg[n] = sum over edges (dst=n) of feat[src]; warp per node
// ---------------------------------------------------------------------------
__global__ void k_gather(const float* __restrict__ feat,
                         const int* __restrict__ csr, const int* __restrict__ off,
                         float* __restrict__ agg, int N)
{
    int g = blockIdx.x * blockDim.x + threadIdx.x;
    int n = g >> 5, lane = g & 31;
    if (n >= N) return;
    int s0 = off[n], s1 = off[n + 1];
    float4 acc = make_float4(0.f, 0.f, 0.f, 0.f);
    for (int base = s0; base < s1; base += 32) {
        int cnt = min(32, s1 - base);
        int idx = (base + lane < s1) ? csr[base + lane] : 0;
#pragma unroll 4
        for (int j = 0; j < cnt; ++j) {
            int s = __shfl_sync(0xFFFFFFFFu, idx, j);
            float4 v = *reinterpret_cast<const float4*>(&feat[(size_t)s * DH + lane * 4]);
            acc.x += v.x; acc.y += v.y; acc.z += v.z; acc.w += v.w;
        }
    }
    *reinterpret_cast<float4*>(&agg[(size_t)n * DH + lane * 4]) = acc;
}

// ---------------------------------------------------------------------------
// weight prep: transpose [k][n] -> [n][k], split to bf16 hi/lo. 8 units.
// ---------------------------------------------------------------------------
struct WSrc { const float* p[8]; };

__global__ void k_wprep(WSrc w,
                        __nv_bfloat16* __restrict__ oh,
                        __nv_bfloat16* __restrict__ ol)
{
    int u = blockIdx.y;
    int i = blockIdx.x * 256 + threadIdx.x;
    int n = i >> 7, k = i & 127;
    float v = w.p[u][(size_t)k * DH + n];
    __nv_bfloat16 h = __float2bfloat16(v);
    oh[(size_t)u * 16384 + i] = h;
    ol[(size_t)u * 16384 + i] = __float2bfloat16(v - __bfloat162float(h));
}

// ---------------------------------------------------------------------------
// mma.sync bf16 GEMM, error-compensated split (hi*hi + hi*lo + lo*hi).
// 512 threads, 16 warps, warp tile 16x64 (8 m-groups x 2 n-groups).
// ---------------------------------------------------------------------------
__global__ __launch_bounds__(512)
void k_gemm_mma(const float* __restrict__ a0f,
                const __nv_bfloat16* __restrict__ a0h, const __nv_bfloat16* __restrict__ a0l,
                const __nv_bfloat16* __restrict__ w0h, const __nv_bfloat16* __restrict__ w0l,
                const float* __restrict__ a1f,
                const __nv_bfloat16* __restrict__ a1h, const __nv_bfloat16* __restrict__ a1l,
                const __nv_bfloat16* __restrict__ w1h, const __nv_bfloat16* __restrict__ w1l,
                const float* __restrict__ bias,
                float* __restrict__ cf,
                __nv_bfloat16* __restrict__ chi, __nv_bfloat16* __restrict__ clo,
                int M, int relu)
{
    extern __shared__ __nv_bfloat16 sm[];
    __nv_bfloat16* sAh = sm;
    __nv_bfloat16* sAl = sAh + 128 * PADK;
    __nv_bfloat16* sBh = sAl + 128 * PADK;
    __nv_bfloat16* sBl = sBh + 128 * PADK;

    const int tid  = threadIdx.x;
    const int wid  = tid >> 5;
    const int lane = tid & 31;
    const int m0   = blockIdx.x * MTILE;
    const int wm   = (wid >> 1) * 16;
    const int wn   = (wid & 1) * 64;

    const uint32_t uAh = smem_to_u32(sAh);
    const uint32_t uAl = smem_to_u32(sAl);
    const uint32_t uBh = smem_to_u32(sBh);
    const uint32_t uBl = smem_to_u32(sBl);

    float acc[8][4];
#pragma unroll
    for (int ni = 0; ni < 8; ++ni)
#pragma unroll
        for (int q = 0; q < 4; ++q) acc[ni][q] = 0.f;

#pragma unroll 1
    for (int phase = 0; phase < 2; ++phase) {
        const float*         Af = phase ? a1f : a0f;
        const __nv_bfloat16* Ah = phase ? a1h : a0h;
        const __nv_bfloat16* Al = phase ? a1l : a0l;
        const __nv_bfloat16* Wh = phase ? w1h : w0h;
        const __nv_bfloat16* Wl = phase ? w1l : w0l;
        if (Af == nullptr && Ah == nullptr) break;

        __syncthreads();
#pragma unroll
        for (int it = 0; it < 4; ++it) {
            int idx = tid + it * 512;          // 0..2047 uint4 slots
            int row = idx >> 4;
            int c8  = (idx & 15) << 3;
            size_t soff = (size_t)row * PADK + c8;
            uint4 vh = make_uint4(0, 0, 0, 0), vl = vh;
            if (m0 + row < M) {
                if (Af) {
                    const float* ap = Af + (size_t)(m0 + row) * DH + c8;
                    float4 f0 = *reinterpret_cast<const float4*>(ap);
                    float4 f1 = *reinterpret_cast<const float4*>(ap + 4);
                    split2(f0.x, f0.y, vh.x, vl.x);
                    split2(f0.z, f0.w, vh.y, vl.y);
                    split2(f1.x, f1.y, vh.z, vl.z);
                    split2(f1.z, f1.w, vh.w, vl.w);
                } else {
                    vh = *reinterpret_cast<const uint4*>(Ah + (size_t)(m0 + row) * DH + c8);
                    vl = *reinterpret_cast<const uint4*>(Al + (size_t)(m0 + row) * DH + c8);
                }
            }
            *reinterpret_cast<uint4*>(sAh + soff) = vh;
            *reinterpret_cast<uint4*>(sAl + soff) = vl;
            *reinterpret_cast<uint4*>(sBh + soff) =
                *reinterpret_cast<const uint4*>(Wh + (size_t)row * DH + c8);
            *reinterpret_cast<uint4*>(sBl + soff) =
                *reinterpret_cast<const uint4*>(Wl + (size_t)row * DH + c8);
        }
        __syncthreads();

#pragma unroll 1
        for (int kc = 0; kc < 8; ++kc) {
            int k0 = kc * 16;
            uint32_t a_off = (uint32_t)(((wm + (lane & 15)) * PADK + k0 + (lane >> 4) * 8) * 2);
            uint32_t ah[4], al[4];
            ldsm_x4(ah, uAh + a_off);
            ldsm_x4(al, uAl + a_off);
            uint32_t b_off = (uint32_t)(((wn + (lane & 7)) * PADK + k0 + ((lane >> 3) & 1) * 8) * 2);
            uint32_t bh[8][2], bl[8][2];
#pragma unroll
            for (int ni = 0; ni < 8; ++ni) {
                uint32_t o = b_off + (uint32_t)(ni * 8 * PADK * 2);
                ldsm_x2(bh[ni], uBh + o);
                ldsm_x2(bl[ni], uBl + o);
            }
#pragma unroll
            for (int ni = 0; ni < 8; ++ni) {
                mma16816(acc[ni], ah, bh[ni]);
                mma16816(acc[ni], ah, bl[ni]);
                mma16816(acc[ni], al, bh[ni]);
            }
        }
    }

    const int gid = lane >> 2, tig = lane & 3;
#pragma unroll
    for (int half = 0; half < 2; ++half) {
        int r = wm + gid + half * 8;
        int m = m0 + r;
        if (m >= M) continue;
#pragma unroll
        for (int ni = 0; ni < 8; ++ni) {
            int col = wn + ni * 8 + tig * 2;
            float v0 = acc[ni][half * 2];
            float v1 = acc[ni][half * 2 + 1];
            if (bias) { v0 += bias[col]; v1 += bias[col + 1]; }
            if (relu) { v0 = fmaxf(v0, 0.f); v1 = fmaxf(v1, 0.f); }
            if (cf)
                *reinterpret_cast<float2*>(cf + (size_t)m * DH + col) = make_float2(v0, v1);
            if (chi) {
                uint32_t ph, pl;
                split2(v0, v1, ph, pl);
                *reinterpret_cast<uint32_t*>(chi + (size_t)m * DH + col) = ph;
                *reinterpret_cast<uint32_t*>(clo + (size_t)m * DH + col) = pl;
            }
        }
    }
}

// ---------------------------------------------------------------------------
// Merged head GEMM: A (h2 hi/lo) loaded once; 4 weight units; fp16 S out.
// 512 threads, 16 warps, warp tile 16x64.
// ---------------------------------------------------------------------------
__global__ __launch_bounds__(512)
void k_gemm_head(const __nv_bfloat16* __restrict__ ah_, const __nv_bfloat16* __restrict__ al_,
                 const __nv_bfloat16* __restrict__ Wh4, const __nv_bfloat16* __restrict__ Wl4,
                 __half* __restrict__ S, int M)
{
    extern __shared__ __nv_bfloat16 sm[];
    __nv_bfloat16* sAh = sm;
    __nv_bfloat16* sAl = sAh + 128 * PADK;
    __nv_bfloat16* sBh = sAl + 128 * PADK;
    __nv_bfloat16* sBl = sBh + 128 * PADK;

    const int tid  = threadIdx.x;
    const int wid  = tid >> 5;
    const int lane = tid & 31;
    const int m0   = blockIdx.x * MTILE;
    const int wm   = (wid >> 1) * 16;
    const int wn   = (wid & 1) * 64;

    const uint32_t uAh = smem_to_u32(sAh);
    const uint32_t uAl = smem_to_u32(sAl);
    const uint32_t uBh = smem_to_u32(sBh);
    const uint32_t uBl = smem_to_u32(sBl);

#pragma unroll
    for (int it = 0; it < 4; ++it) {
        int idx = tid + it * 512;
        int row = idx >> 4;
        int c8  = (idx & 15) << 3;
        size_t soff = (size_t)row * PADK + c8;
        uint4 vh = make_uint4(0, 0, 0, 0), vl = vh;
        if (m0 + row < M) {
            vh = *reinterpret_cast<const uint4*>(ah_ + (size_t)(m0 + row) * DH + c8);
            vl = *reinterpret_cast<const uint4*>(al_ + (size_t)(m0 + row) * DH + c8);
        }
        *reinterpret_cast<uint4*>(sAh + soff) = vh;
        *reinterpret_cast<uint4*>(sAl + soff) = vl;
    }

    const int gid = lane >> 2, tig = lane & 3;

#pragma unroll 1
    for (int u = 0; u < 4; ++u) {
        const __nv_bfloat16* Wh = Wh4 + (size_t)u * 16384;
        const __nv_bfloat16* Wl = Wl4 + (size_t)u * 16384;

        __syncthreads();
#pragma unroll
        for (int it = 0; it < 4; ++it) {
            int idx = tid + it * 512;
            int row = idx >> 4;
            int c8  = (idx & 15) << 3;
            size_t soff = (size_t)row * PADK + c8;
            *reinterpret_cast<uint4*>(sBh + soff) =
                *reinterpret_cast<const uint4*>(Wh + (size_t)row * DH + c8);
            *reinterpret_cast<uint4*>(sBl + soff) =
                *reinterpret_cast<const uint4*>(Wl + (size_t)row * DH + c8);
        }
        __syncthreads();

        float acc[8][4];
#pragma unroll
        for (int ni = 0; ni < 8; ++ni)
#pragma unroll
            for (int q = 0; q < 4; ++q) acc[ni][q] = 0.f;

#pragma unroll 1
        for (int kc = 0; kc < 8; ++kc) {
            int k0 = kc * 16;
            uint32_t a_off = (uint32_t)(((wm + (lane & 15)) * PADK + k0 + (lane >> 4) * 8) * 2);
            uint32_t ah[4], al[4];
            ldsm_x4(ah, uAh + a_off);
            ldsm_x4(al, uAl + a_off);
            uint32_t b_off = (uint32_t)(((wn + (lane & 7)) * PADK + k0 + ((lane >> 3) & 1) * 8) * 2);
            uint32_t bh[8][2], bl[8][2];
#pragma unroll
            for (int ni = 0; ni < 8; ++ni) {
                uint32_t o = b_off + (uint32_t)(ni * 8 * PADK * 2);
                ldsm_x2(bh[ni], uBh + o);
                ldsm_x2(bl[ni], uBl + o);
            }
#pragma unroll
            for (int ni = 0; ni < 8; ++ni) {
                mma16816(acc[ni], ah, bh[ni]);
                mma16816(acc[ni], ah, bl[ni]);
                mma16816(acc[ni], al, bh[ni]);
            }
        }

#pragma unroll
        for (int half = 0; half < 2; ++half) {
            int r = wm + gid + half * 8;
            int m = m0 + r;
            if (m >= M) continue;
#pragma unroll
            for (int ni = 0; ni < 8; ++ni) {
                int col = wn + ni * 8 + tig * 2;
                __half2 hv = __floats2half2_rn(acc[ni][half * 2], acc[ni][half * 2 + 1]);
                *reinterpret_cast<__half2*>(S + (size_t)m * 512 + u * 128 + col) = hv;
            }
        }
    }
}

// ---------------------------------------------------------------------------
// Edge head: warp per edge, fp16 S table
// ---------------------------------------------------------------------------
__global__ __launch_bounds__(256)
void k_edge(const int* __restrict__ ei,
            const __half* __restrict__ S,
            const float* __restrict__ bm1, const float* __restrict__ Wm2,
            const float* __restrict__ bm2,
            const float* __restrict__ bv1, const float* __restrict__ Wv2,
            const float* __restrict__ bv2,
            float* __restrict__ outMean, float* __restrict__ outVar, int E)
{
    int g = blockIdx.x * blockDim.x + threadIdx.x;
    int e = g >> 5, lane = g & 31;
    if (e >= E) return;

    float4 c_bm1 = *reinterpret_cast<const float4*>(&bm1[lane * 4]);
    float4 c_wm2 = *reinterpret_cast<const float4*>(&Wm2[lane * 4]);
    float4 c_bv1 = *reinterpret_cast<const float4*>(&bv1[lane * 4]);
    float4 c_wv2 = *reinterpret_cast<const float4*>(&Wv2[lane * 4]);

    int s = ei[e];
    int d = ei[(size_t)E + e];
    const __half* Sp = S + (size_t)s * 512;
    const __half* Dp = S + (size_t)d * 512;

    __half2 am2[2], cv2[2], bm2h[2], dv2[2];
    *reinterpret_cast<uint2*>(am2)  = *reinterpret_cast<const uint2*>(Sp + lane * 4);
    *reinterpret_cast<uint2*>(cv2)  = *reinterpret_cast<const uint2*>(Sp + 128 + lane * 4);
    *reinterpret_cast<uint2*>(bm2h) = *reinterpret_cast<const uint2*>(Dp + 256 + lane * 4);
    *reinterpret_cast<uint2*>(dv2)  = *reinterpret_cast<const uint2*>(Dp + 384 + lane * 4);

    float2 am0 = __half22float2(am2[0]),  am1 = __half22float2(am2[1]);
    float2 cv0 = __half22float2(cv2[0]),  cv1 = __half22float2(cv2[1]);
    float2 bm0 = __half22float2(bm2h[0]), bm1f = __half22float2(bm2h[1]);
    float2 dv0 = __half22float2(dv2[0]),  dv1 = __half22float2(dv2[1]);

    float pm = fmaxf(am0.x + bm0.x + c_bm1.x, 0.f) * c_wm2.x
             + fmaxf(am0.y + bm0.y + c_bm1.y, 0.f) * c_wm2.y
             + fmaxf(am1.x + bm1f.x + c_bm1.z, 0.f) * c_wm2.z
             + fmaxf(am1.y + bm1f.y + c_bm1.w, 0.f) * c_wm2.w;
    float pv = fmaxf(cv0.x + dv0.x + c_bv1.x, 0.f) * c_wv2.x
             + fmaxf(cv0.y + dv0.y + c_bv1.y, 0.f) * c_wv2.y
             + fmaxf(cv1.x + dv1.x + c_bv1.z, 0.f) * c_wv2.z
             + fmaxf(cv1.y + dv1.y + c_bv1.w, 0.f) * c_wv2.w;

#pragma unroll
    for (int off = 16; off > 0; off >>= 1) {
        pm += __shfl_xor_sync(0xFFFFFFFFu, pm, off);
        pv += __shfl_xor_sync(0xFFFFFFFFu, pv, off);
    }
    if (lane == 0) {
        outMean[e] = pm + bm2[0];
        outVar[e]  = expf(0.5f * (pv + bv2[0]));
    }
}

// ---------------------------------------------------------------------------
// kernel_launch
// ---------------------------------------------------------------------------
extern "C" void kernel_launch(void* const* d_in, const int* in_sizes, int n_in,
                              void* d_out, int out_size)
{
    const float* x       = (const float*)d_in[0];
    const int*   ei      = (const int*)d_in[1];
    const float* W1_rel  = (const float*)d_in[2];
    const float* b1      = (const float*)d_in[3];
    const float* W1_root = (const float*)d_in[4];
    const float* W2_rel  = (const float*)d_in[5];
    const float* b2      = (const float*)d_in[6];
    const float* W2_root = (const float*)d_in[7];
    const float* Wm1     = (const float*)d_in[8];
    const float* bm1     = (const float*)d_in[9];
    const float* Wm2     = (const float*)d_in[10];
    const float* bm2     = (const float*)d_in[11];
    const float* Wv1     = (const float*)d_in[12];
    const float* bv1     = (const float*)d_in[13];
    const float* Wv2     = (const float*)d_in[14];
    const float* bv2     = (const float*)d_in[15];

    int N = in_sizes[0] / DH;     // 50000
    int E = in_sizes[1] / 2;      // 800000
    float* out   = (float*)d_out;
    int    Ehalf = out_size / 2;

    float *agg, *h1;
    __half* S;
    __nv_bfloat16 *h1h, *h1l, *h2h, *h2l, *Wh, *Wl;
    int *deg, *off, *cursor, *csr, *blk;
    cudaGetSymbolAddress((void**)&agg,    g_agg);
    cudaGetSymbolAddress((void**)&h1,     g_h1);
    cudaGetSymbolAddress((void**)&S,      g_S);
    cudaGetSymbolAddress((void**)&h1h,    g_h1h);
    cudaGetSymbolAddress((void**)&h1l,    g_h1l);
    cudaGetSymbolAddress((void**)&h2h,    g_h2h);
    cudaGetSymbolAddress((void**)&h2l,    g_h2l);
    cudaGetSymbolAddress((void**)&Wh,     g_Wh);
    cudaGetSymbolAddress((void**)&Wl,     g_Wl);
    cudaGetSymbolAddress((void**)&deg,    g_deg);
    cudaGetSymbolAddress((void**)&off,    g_off);
    cudaGetSymbolAddress((void**)&cursor, g_cursor);
    cudaGetSymbolAddress((void**)&csr,    g_csr);
    cudaGetSymbolAddress((void**)&blk,    g_blk);

    const int DYN_SMEM = 4 * 128 * PADK * 2;   // 139264 B
    static int smem_set = 0;
    if (!smem_set) {
        cudaFuncSetAttribute(k_gemm_mma,  cudaFuncAttributeMaxDynamicSharedMemorySize, DYN_SMEM);
        cudaFuncSetAttribute(k_gemm_head, cudaFuncAttributeMaxDynamicSharedMemorySize, DYN_SMEM);
        smem_set = 1;
    }

    int gemmB   = (N + MTILE - 1) / MTILE;
    int edgeB   = (E * 32 + 255) / 256;
    int gatherB = (N * 32 + 255) / 256;
    int eB      = (E + 255) / 256;
    int scanB   = (N + 1023) / 1024;           // 49 for N=50000

    // Weight prep
    WSrc ws;
    ws.p[0] = W1_rel;  ws.p[1] = W1_root;
    ws.p[2] = W2_rel;  ws.p[3] = W2_root;
    ws.p[4] = Wm1;     ws.p[5] = Wv1;
    ws.p[6] = Wm1 + 128 * DH;  ws.p[7] = Wv1 + 128 * DH;
    k_wprep<<<dim3(64, 8), 256>>>(ws, Wh, Wl);

    // CSR build (per launch; reused by both layers)
    k_zeroi<<<(N + 256) / 256, 256>>>(deg, N + 1);
    k_hist<<<eB, 256>>>(ei, E, deg);
    k_scan1<<<scanB, 1024>>>(deg, off, blk, N);
    k_scan2<<<1, 64>>>(blk, off, scanB, N);
    k_scan3<<<scanB, 1024>>>(off, cursor, blk, N);
    k_fill<<<eB, 256>>>(ei, E, cursor, csr);

    // Layer 1
    k_gather<<<gatherB, 256>>>(x, csr, off, agg, N);
    k_gemm_mma<<<gemmB, 512, DYN_SMEM>>>(
        agg, nullptr, nullptr, Wh + 0 * 16384, Wl + 0 * 16384,
        x,   nullptr, nullptr, Wh + 1 * 16384, Wl + 1 * 16384,
        b1, h1, h1h, h1l, N, 1);

    // Layer 2
    k_gather<<<gatherB, 256>>>(h1, csr, off, agg, N);
    k_gemm_mma<<<gemmB, 512, DYN_SMEM>>>(
        agg,     nullptr, nullptr, Wh + 2 * 16384, Wl + 2 * 16384,
        nullptr, h1h,     h1l,     Wh + 3 * 16384, Wl + 3 * 16384,
        b2, nullptr, h2h, h2l, N, 1);

    // Head node tables
    k_gemm_head<<<gemmB, 512, DYN_SMEM>>>(h2h, h2l,
                                          Wh + 4 * 16384, Wl + 4 * 16384, S, N);

    // Edge heads
    k_edge<<<edgeB, 256>>>(ei, S, bm1, Wm2, bm2, bv1, Wv2, bv2,
                           out, out + Ehalf, E);
}

// round 15
// speedup vs baseline: 2.2455x; 1.0927x over previous
#include <cuda_runtime.h>
#include <cuda_bf16.h>
#include <cuda_fp16.h>
#include <math.h>
#include <stdint.h>

#define NMAX 50000
#define EMAX 800000
#define DH   128
#define MTILE 128
#define PADK 136      // bf16 elements per padded SMEM row (272 B)

// ---------------------------------------------------------------------------
// Scratch (__device__ globals; allocation-free rule)
// ---------------------------------------------------------------------------
__device__ float g_agg[(size_t)NMAX * DH];
__device__ float g_h1 [(size_t)NMAX * DH];
__device__ __half g_S [(size_t)NMAX * 512];   // fp16 [Am|Cv|Bm|Dv] per node

__device__ __nv_bfloat16 g_h1h [(size_t)NMAX * DH];
__device__ __nv_bfloat16 g_h1l [(size_t)NMAX * DH];
__device__ __nv_bfloat16 g_h2h [(size_t)NMAX * DH];
__device__ __nv_bfloat16 g_h2l [(size_t)NMAX * DH];
__device__ __nv_bfloat16 g_Wh[8 * 128 * 128];
__device__ __nv_bfloat16 g_Wl[8 * 128 * 128];

// CSR scratch
__device__ int g_deg   [NMAX + 64];
__device__ int g_off   [NMAX + 64];
__device__ int g_cursor[NMAX + 64];
__device__ int g_csr   [EMAX];
__device__ int g_csre  [EMAX];     // edge id per CSR slot
__device__ int g_blk   [128];      // per-block sums for the scan

// ---------------------------------------------------------------------------
// helpers
// ---------------------------------------------------------------------------
__device__ __forceinline__ uint32_t smem_to_u32(const void* p) {
    uint32_t a;
    asm("{ .reg .u64 t; cvta.to.shared.u64 t, %1; cvt.u32.u64 %0, t; }"
        : "=r"(a) : "l"(p));
    return a;
}
__device__ __forceinline__ void ldsm_x4(uint32_t* r, uint32_t addr) {
    asm volatile("ldmatrix.sync.aligned.m8n8.x4.shared.b16 {%0,%1,%2,%3}, [%4];"
                 : "=r"(r[0]), "=r"(r[1]), "=r"(r[2]), "=r"(r[3]) : "r"(addr));
}
__device__ __forceinline__ void mma16816(float* c, const uint32_t* a, const uint32_t* b) {
    asm volatile(
        "mma.sync.aligned.m16n8k16.row.col.f32.bf16.bf16.f32 "
        "{%0,%1,%2,%3}, {%4,%5,%6,%7}, {%8,%9}, {%0,%1,%2,%3};"
        : "+f"(c[0]), "+f"(c[1]), "+f"(c[2]), "+f"(c[3])
        : "r"(a[0]), "r"(a[1]), "r"(a[2]), "r"(a[3]), "r"(b[0]), "r"(b[1]));
}
__device__ __forceinline__ void split2(float v0, float v1, uint32_t& hi, uint32_t& lo)
{
    __nv_bfloat162 h;
    h.x = __float2bfloat16(v0);
    h.y = __float2bfloat16(v1);
    __nv_bfloat162 l;
    l.x = __float2bfloat16(v0 - __bfloat162float(h.x));
    l.y = __float2bfloat16(v1 - __bfloat162float(h.y));
    hi = *reinterpret_cast<uint32_t*>(&h);
    lo = *reinterpret_cast<uint32_t*>(&l);
}

// ---------------------------------------------------------------------------
// CSR build
// ---------------------------------------------------------------------------
__global__ void k_zeroi(int* __restrict__ p, int n)
{
    int i = blockIdx.x * blockDim.x + threadIdx.x;
    if (i < n) p[i] = 0;
}

__global__ void k_hist(const int* __restrict__ ei, int E, int* __restrict__ deg)
{
    int e = blockIdx.x * blockDim.x + threadIdx.x;
    if (e < E) atomicAdd(&deg[ei[(size_t)E + e]], 1);
}

__global__ void k_scan1(const int* __restrict__ deg, int* __restrict__ off,
                        int* __restrict__ blk, int N)
{
    __shared__ int sWarp[32];
    const int t    = threadIdx.x;
    const int lane = t & 31;
    const int w    = t >> 5;
    int i = blockIdx.x * 1024 + t;
    int v = (i < N) ? deg[i] : 0;

    int x = v;
#pragma unroll
    for (int d = 1; d < 32; d <<= 1) {
        int y = __shfl_up_sync(0xFFFFFFFFu, x, d);
        if (lane >= d) x += y;
    }
    if (lane == 31) sWarp[w] = x;
    __syncthreads();
    if (w == 0) {
        int s = sWarp[lane];
#pragma unroll
        for (int d = 1; d < 32; d <<= 1) {
            int y = __shfl_up_sync(0xFFFFFFFFu, s, d);
            if (lane >= d) s += y;
        }
        sWarp[lane] = s;
    }
    __syncthreads();
    int warpBase = (w > 0) ? sWarp[w - 1] : 0;
    if (i < N) off[i] = warpBase + (x - v);
    if (t == 1023) blk[blockIdx.x] = sWarp[31];
}

__global__ void k_scan2(int* __restrict__ blk, int* __restrict__ off, int nB, int N)
{
    const int t = threadIdx.x;   // 64 threads
    int v = (t < nB) ? blk[t] : 0;
    int x = v;
#pragma unroll
    for (int d = 1; d < 32; d <<= 1) {
        int y = __shfl_up_sync(0xFFFFFFFFu, x, d);
        if ((t & 31) >= d) x += y;
    }
    __shared__ int sw[2];
    if ((t & 31) == 31) sw[t >> 5] = x;
    __syncthreads();
    int base = (t >= 32) ? sw[0] : 0;
    int excl = base + x - v;
    if (t < nB) blk[t] = excl;
    if (t == 63) off[N] = base + ((nB > 32) ? sw[1] : ((nB > 0) ? sw[0] : 0));
}

__global__ void k_scan3(int* __restrict__ off, int* __restrict__ cursor,
                        const int* __restrict__ blk, int N)
{
    int i = blockIdx.x * 1024 + threadIdx.x;
    if (i < N) {
        int o = off[i] + blk[blockIdx.x];
        off[i] = o;
        cursor[i] = o;
    }
}

__global__ void k_fill(const int* __restrict__ ei, int E,
                       int* __restrict__ cursor,
                       int* __restrict__ csr, int* __restrict__ csre)
{
    int e = blockIdx.x * blockDim.x + threadIdx.x;
    if (e >= E) return;
    int s = ei[e];
    int d = ei[(size_t)E + e];
    int pos = atomicAdd(&cursor[d], 1);
    csr[pos]  = s;
    csre[pos] = e;
}

// ---------------------------------------------------------------------------
// gather-reduce: agg[n] = sum over edges (dst=n) of feat[src]; warp per node
// ---------------------------------------------------------------------------
__global__ void k_gather(const float* __restrict__ feat,
                         const int* __restrict__ csr, const int* __restrict__ off,
                         float* __restrict__ agg, int N)
{
    int g = blockIdx.x * blockDim.x + threadIdx.x;
    int n = g >> 5, lane = g & 31;
    if (n >= N) return;
    int s0 = off[n], s1 = off[n + 1];
    float4 acc = make_float4(0.f, 0.f, 0.f, 0.f);
    for (int base = s0; base < s1; base += 32) {
        int cnt = min(32, s1 - base);
        int idx = (base + lane < s1) ? csr[base + lane] : 0;
#pragma unroll 4
        for (int j = 0; j < cnt; ++j) {
            int s = __shfl_sync(0xFFFFFFFFu, idx, j);
            float4 v = *reinterpret_cast<const float4*>(&feat[(size_t)s * DH + lane * 4]);
            acc.x += v.x; acc.y += v.y; acc.z += v.z; acc.w += v.w;
        }
    }
    *reinterpret_cast<float4*>(&agg[(size_t)n * DH + lane * 4]) = acc;
}

// ---------------------------------------------------------------------------
// weight prep: transpose [k][n] -> [n][k], split to bf16 hi/lo. 8 units.
// ---------------------------------------------------------------------------
struct WSrc { const float* p[8]; };

__global__ void k_wprep(WSrc w,
                        __nv_bfloat16* __restrict__ oh,
                        __nv_bfloat16* __restrict__ ol)
{
    int u = blockIdx.y;
    int i = blockIdx.x * 256 + threadIdx.x;
    int n = i >> 7, k = i & 127;
    float v = w.p[u][(size_t)k * DH + n];
    __nv_bfloat16 h = __float2bfloat16(v);
    oh[(size_t)u * 16384 + i] = h;
    ol[(size_t)u * 16384 + i] = __float2bfloat16(v - __bfloat162float(h));
}

// ---------------------------------------------------------------------------
// mma.sync bf16 GEMM, error-compensated split (hi*hi + hi*lo + lo*hi).
// 512 threads, 16 warps, warp tile 16x64. Paired-ni ldmatrix.x4 for B:
//   lanes 0-7: (ni, k0) rows; 8-15: (ni, k0+8); 16-23: (ni+1, k0); 24-31: (ni+1, k0+8)
// ---------------------------------------------------------------------------
__global__ __launch_bounds__(512)
void k_gemm_mma(const float* __restrict__ a0f,
                const __nv_bfloat16* __restrict__ a0h, const __nv_bfloat16* __restrict__ a0l,
                const __nv_bfloat16* __restrict__ w0h, const __nv_bfloat16* __restrict__ w0l,
                const float* __restrict__ a1f,
                const __nv_bfloat16* __restrict__ a1h, const __nv_bfloat16* __restrict__ a1l,
                const __nv_bfloat16* __restrict__ w1h, const __nv_bfloat16* __restrict__ w1l,
                const float* __restrict__ bias,
                float* __restrict__ cf,
                __nv_bfloat16* __restrict__ chi, __nv_bfloat16* __restrict__ clo,
                int M, int relu)
{
    extern __shared__ __nv_bfloat16 sm[];
    __nv_bfloat16* sAh = sm;
    __nv_bfloat16* sAl = sAh + 128 * PADK;
    __nv_bfloat16* sBh = sAl + 128 * PADK;
    __nv_bfloat16* sBl = sBh + 128 * PADK;

    const int tid  = threadIdx.x;
    const int wid  = tid >> 5;
    const int lane = tid & 31;
    const int m0   = blockIdx.x * MTILE;
    const int wm   = (wid >> 1) * 16;
    const int wn   = (wid & 1) * 64;

    const uint32_t uAh = smem_to_u32(sAh);
    const uint32_t uAl = smem_to_u32(sAl);
    const uint32_t uBh = smem_to_u32(sBh);
    const uint32_t uBl = smem_to_u32(sBl);

    float acc[8][4];
#pragma unroll
    for (int ni = 0; ni < 8; ++ni)
#pragma unroll
        for (int q = 0; q < 4; ++q) acc[ni][q] = 0.f;

#pragma unroll 1
    for (int phase = 0; phase < 2; ++phase) {
        const float*         Af = phase ? a1f : a0f;
        const __nv_bfloat16* Ah = phase ? a1h : a0h;
        const __nv_bfloat16* Al = phase ? a1l : a0l;
        const __nv_bfloat16* Wh = phase ? w1h : w0h;
        const __nv_bfloat16* Wl = phase ? w1l : w0l;
        if (Af == nullptr && Ah == nullptr) break;

        __syncthreads();
#pragma unroll
        for (int it = 0; it < 4; ++it) {
            int idx = tid + it * 512;          // 0..2047 uint4 slots
            int row = idx >> 4;
            int c8  = (idx & 15) << 3;
            size_t soff = (size_t)row * PADK + c8;
            uint4 vh = make_uint4(0, 0, 0, 0), vl = vh;
            if (m0 + row < M) {
                if (Af) {
                    const float* ap = Af + (size_t)(m0 + row) * DH + c8;
                    float4 f0 = *reinterpret_cast<const float4*>(ap);
                    float4 f1 = *reinterpret_cast<const float4*>(ap + 4);
                    split2(f0.x, f0.y, vh.x, vl.x);
                    split2(f0.z, f0.w, vh.y, vl.y);
                    split2(f1.x, f1.y, vh.z, vl.z);
                    split2(f1.z, f1.w, vh.w, vl.w);
                } else {
                    vh = *reinterpret_cast<const uint4*>(Ah + (size_t)(m0 + row) * DH + c8);
                    vl = *reinterpret_cast<const uint4*>(Al + (size_t)(m0 + row) * DH + c8);
                }
            }
            *reinterpret_cast<uint4*>(sAh + soff) = vh;
            *reinterpret_cast<uint4*>(sAl + soff) = vl;
            *reinterpret_cast<uint4*>(sBh + soff) =
                *reinterpret_cast<const uint4*>(Wh + (size_t)row * DH + c8);
            *reinterpret_cast<uint4*>(sBl + soff) =
                *reinterpret_cast<const uint4*>(Wl + (size_t)row * DH + c8);
        }
        __syncthreads();

#pragma unroll 1
        for (int kc = 0; kc < 8; ++kc) {
            int k0 = kc * 16;
            uint32_t a_off = (uint32_t)(((wm + (lane & 15)) * PADK + k0 + (lane >> 4) * 8) * 2);
            uint32_t ah[4], al[4];
            ldsm_x4(ah, uAh + a_off);
            ldsm_x4(al, uAl + a_off);
            // paired-ni B fragments
            uint32_t b4_off = (uint32_t)(((wn + (lane & 7) + ((lane >> 4) << 3)) * PADK
                                          + k0 + ((lane >> 3) & 1) * 8) * 2);
            uint32_t bh[16], bl[16];
#pragma unroll
            for (int jj = 0; jj < 4; ++jj) {
                uint32_t o = b4_off + (uint32_t)(jj * 16 * PADK * 2);
                ldsm_x4(&bh[jj * 4], uBh + o);
                ldsm_x4(&bl[jj * 4], uBl + o);
            }
#pragma unroll
            for (int ni = 0; ni < 8; ++ni) {
                mma16816(acc[ni], ah, &bh[ni * 2]);
                mma16816(acc[ni], ah, &bl[ni * 2]);
                mma16816(acc[ni], al, &bh[ni * 2]);
            }
        }
    }

    const int gid = lane >> 2, tig = lane & 3;
#pragma unroll
    for (int half = 0; half < 2; ++half) {
        int r = wm + gid + half * 8;
        int m = m0 + r;
        if (m >= M) continue;
#pragma unroll
        for (int ni = 0; ni < 8; ++ni) {
            int col = wn + ni * 8 + tig * 2;
            float v0 = acc[ni][half * 2];
            float v1 = acc[ni][half * 2 + 1];
            if (bias) { v0 += bias[col]; v1 += bias[col + 1]; }
            if (relu) { v0 = fmaxf(v0, 0.f); v1 = fmaxf(v1, 0.f); }
            if (cf)
                *reinterpret_cast<float2*>(cf + (size_t)m * DH + col) = make_float2(v0, v1);
            if (chi) {
                uint32_t ph, pl;
                split2(v0, v1, ph, pl);
                *reinterpret_cast<uint32_t*>(chi + (size_t)m * DH + col) = ph;
                *reinterpret_cast<uint32_t*>(clo + (size_t)m * DH + col) = pl;
            }
        }
    }
}

// ---------------------------------------------------------------------------
// Merged head GEMM: A (h2 hi/lo) loaded once; 4 weight units; fp16 S out.
// ---------------------------------------------------------------------------
__global__ __launch_bounds__(512)
void k_gemm_head(const __nv_bfloat16* __restrict__ ah_, const __nv_bfloat16* __restrict__ al_,
                 const __nv_bfloat16* __restrict__ Wh4, const __nv_bfloat16* __restrict__ Wl4,
                 __half* __restrict__ S, int M)
{
    extern __shared__ __nv_bfloat16 sm[];
    __nv_bfloat16* sAh = sm;
    __nv_bfloat16* sAl = sAh + 128 * PADK;
    __nv_bfloat16* sBh = sAl + 128 * PADK;
    __nv_bfloat16* sBl = sBh + 128 * PADK;

    const int tid  = threadIdx.x;
    const int wid  = tid >> 5;
    const int lane = tid & 31;
    const int m0   = blockIdx.x * MTILE;
    const int wm   = (wid >> 1) * 16;
    const int wn   = (wid & 1) * 64;

    const uint32_t uAh = smem_to_u32(sAh);
    const uint32_t uAl = smem_to_u32(sAl);
    const uint32_t uBh = smem_to_u32(sBh);
    const uint32_t uBl = smem_to_u32(sBl);

#pragma unroll
    for (int it = 0; it < 4; ++it) {
        int idx = tid + it * 512;
        int row = idx >> 4;
        int c8  = (idx & 15) << 3;
        size_t soff = (size_t)row * PADK + c8;
        uint4 vh = make_uint4(0, 0, 0, 0), vl = vh;
        if (m0 + row < M) {
            vh = *reinterpret_cast<const uint4*>(ah_ + (size_t)(m0 + row) * DH + c8);
            vl = *reinterpret_cast<const uint4*>(al_ + (size_t)(m0 + row) * DH + c8);
        }
        *reinterpret_cast<uint4*>(sAh + soff) = vh;
        *reinterpret_cast<uint4*>(sAl + soff) = vl;
    }

    const int gid = lane >> 2, tig = lane & 3;

#pragma unroll 1
    for (int u = 0; u < 4; ++u) {
        const __nv_bfloat16* Wh = Wh4 + (size_t)u * 16384;
        const __nv_bfloat16* Wl = Wl4 + (size_t)u * 16384;

        __syncthreads();
#pragma unroll
        for (int it = 0; it < 4; ++it) {
            int idx = tid + it * 512;
            int row = idx >> 4;
            int c8  = (idx & 15) << 3;
            size_t soff = (size_t)row * PADK + c8;
            *reinterpret_cast<uint4*>(sBh + soff) =
                *reinterpret_cast<const uint4*>(Wh + (size_t)row * DH + c8);
            *reinterpret_cast<uint4*>(sBl + soff) =
                *reinterpret_cast<const uint4*>(Wl + (size_t)row * DH + c8);
        }
        __syncthreads();

        float acc[8][4];
#pragma unroll
        for (int ni = 0; ni < 8; ++ni)
#pragma unroll
            for (int q = 0; q < 4; ++q) acc[ni][q] = 0.f;

#pragma unroll 1
        for (int kc = 0; kc < 8; ++kc) {
            int k0 = kc * 16;
            uint32_t a_off = (uint32_t)(((wm + (lane & 15)) * PADK + k0 + (lane >> 4) * 8) * 2);
            uint32_t ah[4], al[4];
            ldsm_x4(ah, uAh + a_off);
            ldsm_x4(al, uAl + a_off);
            uint32_t b4_off = (uint32_t)(((wn + (lane & 7) + ((lane >> 4) << 3)) * PADK
                                          + k0 + ((lane >> 3) & 1) * 8) * 2);
            uint32_t bh[16], bl[16];
#pragma unroll
            for (int jj = 0; jj < 4; ++jj) {
                uint32_t o = b4_off + (uint32_t)(jj * 16 * PADK * 2);
                ldsm_x4(&bh[jj * 4], uBh + o);
                ldsm_x4(&bl[jj * 4], uBl + o);
            }
#pragma unroll
            for (int ni = 0; ni < 8; ++ni) {
                mma16816(acc[ni], ah, &bh[ni * 2]);
                mma16816(acc[ni], ah, &bl[ni * 2]);
                mma16816(acc[ni], al, &bh[ni * 2]);
            }
        }

#pragma unroll
        for (int half = 0; half < 2; ++half) {
            int r = wm + gid + half * 8;
            int m = m0 + r;
            if (m >= M) continue;
#pragma unroll
            for (int ni = 0; ni < 8; ++ni) {
                int col = wn + ni * 8 + tig * 2;
                __half2 hv = __floats2half2_rn(acc[ni][half * 2], acc[ni][half * 2 + 1]);
                *reinterpret_cast<__half2*>(S + (size_t)m * 512 + u * 128 + col) = hv;
            }
        }
    }
}

// ---------------------------------------------------------------------------
// Edge head, node-centric: warp per dst node; dst half loaded once,
// src half streamed per in-edge; scattered per-edge output.
// ---------------------------------------------------------------------------
__global__ __launch_bounds__(256)
void k_edge2(const int* __restrict__ csr, const int* __restrict__ csre,
             const int* __restrict__ off,
             const __half* __restrict__ S,
             const float* __restrict__ bm1, const float* __restrict__ Wm2,
             const float* __restrict__ bm2,
             const float* __restrict__ bv1, const float* __restrict__ Wv2,
             const float* __restrict__ bv2,
             float* __restrict__ outMean, float* __restrict__ outVar, int N)
{
    int g = blockIdx.x * blockDim.x + threadIdx.x;
    int n = g >> 5, lane = g & 31;
    if (n >= N) return;

    int p0 = off[n], p1 = off[n + 1];
    if (p0 == p1) return;

    float4 c_wm2 = *reinterpret_cast<const float4*>(&Wm2[lane * 4]);
    float4 c_wv2 = *reinterpret_cast<const float4*>(&Wv2[lane * 4]);
    float4 c_bm1 = *reinterpret_cast<const float4*>(&bm1[lane * 4]);
    float4 c_bv1 = *reinterpret_cast<const float4*>(&bv1[lane * 4]);
    float obm = bm2[0], obv = bv2[0];

    // dst half: Bm at +256, Dv at +384; fold bias in
    const __half* Dp = S + (size_t)n * 512;
    __half2 bmx[2], dvx[2];
    *reinterpret_cast<uint2*>(bmx) = *reinterpret_cast<const uint2*>(Dp + 256 + lane * 4);
    *reinterpret_cast<uint2*>(dvx) = *reinterpret_cast<const uint2*>(Dp + 384 + lane * 4);
    float2 b0 = __half22float2(bmx[0]), b1 = __half22float2(bmx[1]);
    float2 d0 = __half22float2(dvx[0]), d1 = __half22float2(dvx[1]);
    float tm0 = b0.x + c_bm1.x, tm1 = b0.y + c_bm1.y;
    float tm2 = b1.x + c_bm1.z, tm3 = b1.y + c_bm1.w;
    float tv0 = d0.x + c_bv1.x, tv1 = d0.y + c_bv1.y;
    float tv2 = d1.x + c_bv1.z, tv3 = d1.y + c_bv1.w;

#pragma unroll 1
    for (int p = p0; p < p1; ++p) {
        int s = csr[p];
        int e = csre[p];
        const __half* Sp = S + (size_t)s * 512;
        __half2 amx[2], cvx[2];
        *reinterpret_cast<uint2*>(amx) = *reinterpret_cast<const uint2*>(Sp + lane * 4);
        *reinterpret_cast<uint2*>(cvx) = *reinterpret_cast<const uint2*>(Sp + 128 + lane * 4);
        float2 a0 = __half22float2(amx[0]), a1 = __half22float2(amx[1]);
        float2 c0 = __half22float2(cvx[0]), c1 = __half22float2(cvx[1]);

        float pm = fmaxf(a0.x + tm0, 0.f) * c_wm2.x
                 + fmaxf(a0.y + tm1, 0.f) * c_wm2.y
                 + fmaxf(a1.x + tm2, 0.f) * c_wm2.z
                 + fmaxf(a1.y + tm3, 0.f) * c_wm2.w;
        float pv = fmaxf(c0.x + tv0, 0.f) * c_wv2.x
                 + fmaxf(c0.y + tv1, 0.f) * c_wv2.y
                 + fmaxf(c1.x + tv2, 0.f) * c_wv2.z
                 + fmaxf(c1.y + tv3, 0.f) * c_wv2.w;

#pragma unroll
        for (int o = 16; o > 0; o >>= 1) {
            pm += __shfl_xor_sync(0xFFFFFFFFu, pm, o);
            pv += __shfl_xor_sync(0xFFFFFFFFu, pv, o);
        }
        if (lane == 0) {
            outMean[e] = pm + obm;
            outVar[e]  = expf(0.5f * (pv + obv));
        }
    }
}

// ---------------------------------------------------------------------------
// kernel_launch
// ---------------------------------------------------------------------------
extern "C" void kernel_launch(void* const* d_in, const int* in_sizes, int n_in,
                              void* d_out, int out_size)
{
    const float* x       = (const float*)d_in[0];
    const int*   ei      = (const int*)d_in[1];
    const float* W1_rel  = (const float*)d_in[2];
    const float* b1      = (const float*)d_in[3];
    const float* W1_root = (const float*)d_in[4];
    const float* W2_rel  = (const float*)d_in[5];
    const float* b2      = (const float*)d_in[6];
    const float* W2_root = (const float*)d_in[7];
    const float* Wm1     = (const float*)d_in[8];
    const float* bm1     = (const float*)d_in[9];
    const float* Wm2     = (const float*)d_in[10];
    const float* bm2     = (const float*)d_in[11];
    const float* Wv1     = (const float*)d_in[12];
    const float* bv1     = (const float*)d_in[13];
    const float* Wv2     = (const float*)d_in[14];
    const float* bv2     = (const float*)d_in[15];

    int N = in_sizes[0] / DH;     // 50000
    int E = in_sizes[1] / 2;      // 800000
    float* out   = (float*)d_out;
    int    Ehalf = out_size / 2;

    float *agg, *h1;
    __half* S;
    __nv_bfloat16 *h1h, *h1l, *h2h, *h2l, *Wh, *Wl;
    int *deg, *off, *cursor, *csr, *csre, *blk;
    cudaGetSymbolAddress((void**)&agg,    g_agg);
    cudaGetSymbolAddress((void**)&h1,     g_h1);
    cudaGetSymbolAddress((void**)&S,      g_S);
    cudaGetSymbolAddress((void**)&h1h,    g_h1h);
    cudaGetSymbolAddress((void**)&h1l,    g_h1l);
    cudaGetSymbolAddress((void**)&h2h,    g_h2h);
    cudaGetSymbolAddress((void**)&h2l,    g_h2l);
    cudaGetSymbolAddress((void**)&Wh,     g_Wh);
    cudaGetSymbolAddress((void**)&Wl,     g_Wl);
    cudaGetSymbolAddress((void**)&deg,    g_deg);
    cudaGetSymbolAddress((void**)&off,    g_off);
    cudaGetSymbolAddress((void**)&cursor, g_cursor);
    cudaGetSymbolAddress((void**)&csr,    g_csr);
    cudaGetSymbolAddress((void**)&csre,   g_csre);
    cudaGetSymbolAddress((void**)&blk,    g_blk);

    const int DYN_SMEM = 4 * 128 * PADK * 2;   // 139264 B
    static int smem_set = 0;
    if (!smem_set) {
        cudaFuncSetAttribute(k_gemm_mma,  cudaFuncAttributeMaxDynamicSharedMemorySize, DYN_SMEM);
        cudaFuncSetAttribute(k_gemm_head, cudaFuncAttributeMaxDynamicSharedMemorySize, DYN_SMEM);
        smem_set = 1;
    }

    int gemmB   = (N + MTILE - 1) / MTILE;
    int gatherB = (N * 32 + 255) / 256;
    int eB      = (E + 255) / 256;
    int scanB   = (N + 1023) / 1024;

    // Weight prep
    WSrc ws;
    ws.p[0] = W1_rel;  ws.p[1] = W1_root;
    ws.p[2] = W2_rel;  ws.p[3] = W2_root;
    ws.p[4] = Wm1;     ws.p[5] = Wv1;
    ws.p[6] = Wm1 + 128 * DH;  ws.p[7] = Wv1 + 128 * DH;
    k_wprep<<<dim3(64, 8), 256>>>(ws, Wh, Wl);

    // CSR build
    k_zeroi<<<(N + 256) / 256, 256>>>(deg, N + 1);
    k_hist<<<eB, 256>>>(ei, E, deg);
    k_scan1<<<scanB, 1024>>>(deg, off, blk, N);
    k_scan2<<<1, 64>>>(blk, off, scanB, N);
    k_scan3<<<scanB, 1024>>>(off, cursor, blk, N);
    k_fill<<<eB, 256>>>(ei, E, cursor, csr, csre);

    // Layer 1
    k_gather<<<gatherB, 256>>>(x, csr, off, agg, N);
    k_gemm_mma<<<gemmB, 512, DYN_SMEM>>>(
        agg, nullptr, nullptr, Wh + 0 * 16384, Wl + 0 * 16384,
        x,   nullptr, nullptr, Wh + 1 * 16384, Wl + 1 * 16384,
        b1, h1, h1h, h1l, N, 1);

    // Layer 2
    k_gather<<<gatherB, 256>>>(h1, csr, off, agg, N);
    k_gemm_mma<<<gemmB, 512, DYN_SMEM>>>(
        agg,     nullptr, nullptr, Wh + 2 * 16384, Wl + 2 * 16384,
        nullptr, h1h,     h1l,     Wh + 3 * 16384, Wl + 3 * 16384,
        b2, nullptr, h2h, h2l, N, 1);

    // Head node tables
    k_gemm_head<<<gemmB, 512, DYN_SMEM>>>(h2h, h2l,
                                          Wh + 4 * 16384, Wl + 4 * 16384, S, N);

    // Edge heads (node-centric)
    k_edge2<<<gatherB, 256>>>(csr, csre, off, S, bm1, Wm2, bm2, bv1, Wv2, bv2,
                              out, out + Ehalf, N);
}